// round 7
// baseline (speedup 1.0000x reference)
#include <cuda_runtime.h>
#include <cstdint>

// ---------------- problem constants ----------------
static constexpr int Bsz = 16384;
// LNB 128K + TCH 16K + WBa 32K + WBb 32K = 208K (+1K align)
static constexpr int SMEM_DYN = 208 * 1024 + 1024;

// ---------------- device scratch ----------------
__device__ float g_Anum[32 * 256];
__device__ float g_c[256];
__device__ float g_cpart[32 * 256];
__device__ float g_W1p[8 * 8  * 512 * 32];   // [l][kb][n(512)][32] swizzled tf32
__device__ float g_W2p[8 * 16 * 256 * 32];   // [l][kb][n(256)][32] swizzled tf32
__device__ float g_Wfp[129 * 256 * 32];      // first-layer packed (kb0 = folded numeric)

// ---------------- PTX helpers ----------------
__device__ __forceinline__ uint32_t sm32(const void* p) {
    uint32_t a;
    asm("{ .reg .u64 t; cvta.to.shared.u64 t, %1; cvt.u32.u64 %0, t; }" : "=r"(a) : "l"(p));
    return a;
}
__device__ __forceinline__ void cpa16(uint32_t dst, const void* src) {
    asm volatile("cp.async.cg.shared.global [%0], [%1], 16;" :: "r"(dst), "l"(src));
}
#define CPA_COMMIT() asm volatile("cp.async.commit_group;" ::: "memory")
#define CPA_WAIT(n)  asm volatile("cp.async.wait_group %0;" :: "n"(n) : "memory")

__device__ __forceinline__ void ldm4(uint32_t (&r)[4], uint32_t addr) {
    asm volatile("ldmatrix.sync.aligned.m8n8.x4.shared.b16 {%0,%1,%2,%3}, [%4];"
                 : "=r"(r[0]), "=r"(r[1]), "=r"(r[2]), "=r"(r[3]) : "r"(addr));
}
__device__ __forceinline__ uint32_t to_tf32(uint32_t v) {
    uint32_t o;
    asm("cvt.rna.tf32.f32 %0, %1;" : "=r"(o) : "f"(__uint_as_float(v)));
    return o;
}
__device__ __forceinline__ float round_tf32(float v) {
    uint32_t o;
    asm("cvt.rna.tf32.f32 %0, %1;" : "=r"(o) : "f"(v));
    return __uint_as_float(o);
}
__device__ __forceinline__ void mma_tf32(float (&d)[4], const uint32_t (&a)[4],
                                         uint32_t b0, uint32_t b1) {
    asm volatile("mma.sync.aligned.m16n8k8.row.col.f32.tf32.tf32.f32 "
                 "{%0,%1,%2,%3}, {%4,%5,%6,%7}, {%8,%9}, {%0,%1,%2,%3};"
                 : "+f"(d[0]), "+f"(d[1]), "+f"(d[2]), "+f"(d[3])
                 : "r"(a[0]), "r"(a[1]), "r"(a[2]), "r"(a[3]), "r"(b0), "r"(b1));
}
__device__ __forceinline__ void st2s(uint32_t addr, float x, float y) {
    asm volatile("st.shared.v2.f32 [%0], {%1, %2};" :: "r"(addr), "f"(x), "f"(y));
}

// ---------------- prep kernels ----------------
__global__ void prep_anum(const float* __restrict__ w_num, const float* __restrict__ W_first) {
    int f = blockIdx.x, j = threadIdx.x;
    const float* Wf = W_first + (size_t)f * 256 * 256 + j;
    const float* wn = w_num + f * 256;
    float acc = 0.f;
    for (int d = 0; d < 256; d++) acc = fmaf(wn[d], Wf[(size_t)d * 256], acc);
    g_Anum[f * 256 + j] = acc;
}
__global__ void prep_c1(const float* __restrict__ b_num, const float* __restrict__ W_first) {
    int b = blockIdx.x, j = threadIdx.x;
    float acc = 0.f;
    const float* W = W_first + (size_t)b * 256 * 256 + j;
    const float* bn = b_num + b * 256;
    for (int k = 0; k < 256; k++) acc = fmaf(bn[k], W[(size_t)k * 256], acc);
    g_cpart[b * 256 + j] = acc;
}
__global__ void prep_c2(const float* __restrict__ b_first) {
    int j = threadIdx.x;
    float acc = b_first[j];
    for (int b = 0; b < 32; b++) acc += g_cpart[b * 256 + j];
    g_c[j] = acc;
}
__global__ void pack_w(const float* __restrict__ src, float* __restrict__ dst, int Ktot, int N) {
    int total = (Ktot / 32) * N * 32;
    for (int i = blockIdx.x * blockDim.x + threadIdx.x; i < total; i += gridDim.x * blockDim.x) {
        int j  = i & 31;
        int n  = (i >> 5) % N;
        int kb = i / (N * 32);
        int k  = (((j >> 2) ^ (n & 7)) << 2) | (j & 3);
        dst[i] = round_tf32(src[(size_t)(kb * 32 + k) * N + n]);
    }
}

// =====================================================================
// Persistent fused network kernel. One CTA = 128 rows, 512 threads, occ 1.
// Weight pipeline: WBa (W1 slices) / WBb (W2 chunks), 1-deep prefetch,
// cp.async.wait_group(1) steady state. Residual h lives in registers.
// =====================================================================
__global__ __launch_bounds__(512, 1) void fused_net(
    const float* __restrict__ xnum, const int* __restrict__ xidx,
    const float* __restrict__ cemb,
    const float* __restrict__ b1g, const float* __restrict__ b2g,
    const float* __restrict__ lng, const float* __restrict__ lnbet,
    const float* __restrict__ gf,  const float* __restrict__ betf,
    const float* __restrict__ Wh,  const float* __restrict__ bh,
    float* __restrict__ out)
{
    extern __shared__ float dsm[];
    __shared__ float red_s[128 * 4], red_q[128 * 4];
    uint32_t raw  = sm32(dsm);
    uint32_t base = (raw + 1023u) & ~1023u;
    const uint32_t LNB = base;             // 128 KB: ln tile, 8 chunks of (128r x 32k)
    const uint32_t TCH = base + 131072u;   //  16 KB: t chunk (128r x 32k)
    const uint32_t WBa = base + 147456u;   //  32 KB: W1 slice
    const uint32_t WBb = base + 180224u;   //  32 KB: W2 chunk

    int tid = threadIdx.x, wid = tid >> 5, lane = tid & 31;
    int bm = blockIdx.x * 128;
    int warp_m = wid & 3, warp_n = wid >> 2;   // GEMM2 / phase0: 4 x 4 (128 x 256)
    int wm1 = wid & 7,    wn1 = wid >> 3;      // GEMM1: 8 x 2 (128 x 32)
    int lr = lane & 7, lh = (lane >> 3) & 1, lg = lane >> 4;

    float hreg[16][4];
#pragma unroll
    for (int t = 0; t < 16; t++)
#pragma unroll
        for (int q = 0; q < 4; q++) hreg[t][q] = 0.f;

    // ================= Phase 0: first GEMM (gathered A, K=4128) ==========
    {
        int ar = tid >> 2, aq = tid & 3, m = bm + ar;
        auto issue = [&](int c, int b) {
            const float* arow;
            if (c == 0) arow = xnum + (size_t)m * 32;
            else {
                int cc = c - 1, f = cc >> 3, d0 = (cc & 7) << 5;
                arow = cemb + (size_t)xidx[m * 16 + f] * 256 + d0;
            }
            uint32_t Ad = base + (uint32_t)b * 16384u + (uint32_t)ar * 128u;
#pragma unroll
            for (int i = 0; i < 2; i++) {
                int g = aq + i * 4;
                cpa16(Ad + (uint32_t)((g ^ (ar & 7)) << 4), arow + g * 4);
            }
            const float4* bsrc = (const float4*)(g_Wfp + (size_t)c * 8192) + tid;
            uint32_t Bd = base + 32768u + (uint32_t)b * 32768u + (uint32_t)tid * 16u;
#pragma unroll
            for (int i = 0; i < 4; i++) cpa16(Bd + (uint32_t)i * 8192u, bsrc + i * 512);
            CPA_COMMIT();
        };
        issue(0, 0);
        issue(1, 1);
#pragma unroll 1
        for (int c = 0; c < 129; c++) {
            if (c + 1 < 129) CPA_WAIT(1); else CPA_WAIT(0);
            __syncthreads();
            uint32_t Ab = base + (uint32_t)(c & 1) * 16384u;
            uint32_t Bb = base + 32768u + (uint32_t)(c & 1) * 32768u;
#pragma unroll
            for (int s = 0; s < 4; s++) {
                uint32_t af[2][4];
#pragma unroll
                for (int i = 0; i < 2; i++) {
                    int R = warp_m * 32 + i * 16 + lr + lh * 8;
                    int g = s * 2 + lg;
                    ldm4(af[i], Ab + (uint32_t)(R * 128 + ((g ^ (R & 7)) << 4)));
#pragma unroll
                    for (int q = 0; q < 4; q++) af[i][q] = to_tf32(af[i][q]);
                }
                uint32_t bf[8][2];
#pragma unroll
                for (int p = 0; p < 4; p++) {
                    int n = warp_n * 64 + p * 16 + lr + lh * 8;
                    int g = s * 2 + lg;
                    uint32_t t4[4];
                    ldm4(t4, Bb + (uint32_t)(n * 128 + ((g ^ (n & 7)) << 4)));
                    bf[2 * p][0] = t4[0]; bf[2 * p + 1][0] = t4[1];
                    bf[2 * p][1] = t4[2]; bf[2 * p + 1][1] = t4[3];
                }
#pragma unroll
                for (int i = 0; i < 2; i++)
#pragma unroll
                    for (int j = 0; j < 8; j++)
                        mma_tf32(hreg[i * 8 + j], af[i], bf[j][0], bf[j][1]);
            }
            __syncthreads();
            if (c + 2 < 129) issue(c + 2, c & 1);
        }
#pragma unroll
        for (int i = 0; i < 2; i++)
#pragma unroll
            for (int j = 0; j < 8; j++) {
                int col = warp_n * 64 + j * 8 + (lane & 3) * 2;
                float b0 = g_c[col], b1 = g_c[col + 1];
                hreg[i * 8 + j][0] += b0; hreg[i * 8 + j][1] += b1;
                hreg[i * 8 + j][2] += b0; hreg[i * 8 + j][3] += b1;
            }
    }

    // ---- weight-slice loaders (1-deep prefetch pipeline) ----
    auto issueW1 = [&](const float* W1) {    // 32KB: [kb(8)][32n][32k] pieces
#pragma unroll
        for (int i = 0; i < 4; i++) {
            int idx = tid + i * 512;
            int piece = idx >> 8, off = idx & 255;
            cpa16(WBa + (uint32_t)idx * 16u, W1 + (size_t)piece * 512 * 32 + off * 4);
        }
        CPA_COMMIT();
    };
    auto issueW2 = [&](const float* W2c) {   // 32KB contiguous
        const float4* src = (const float4*)W2c + tid;
#pragma unroll
        for (int i = 0; i < 4; i++)
            cpa16(WBb + (uint32_t)(tid * 16 + i * 8192), src + i * 512);
        CPA_COMMIT();
    };

    // ---- LN from hreg -> ln smem (tf32-rounded) ----
    auto do_ln = [&](const float* gam, const float* bet) {
        float rs_[4] = {0.f, 0.f, 0.f, 0.f}, rq_[4] = {0.f, 0.f, 0.f, 0.f};
#pragma unroll
        for (int i = 0; i < 2; i++)
#pragma unroll
            for (int j = 0; j < 8; j++) {
                float v0 = hreg[i * 8 + j][0], v1 = hreg[i * 8 + j][1];
                float v2 = hreg[i * 8 + j][2], v3 = hreg[i * 8 + j][3];
                rs_[i * 2 + 0] += v0 + v1;  rq_[i * 2 + 0] += v0 * v0 + v1 * v1;
                rs_[i * 2 + 1] += v2 + v3;  rq_[i * 2 + 1] += v2 * v2 + v3 * v3;
            }
#pragma unroll
        for (int t = 0; t < 4; t++)
#pragma unroll
            for (int o = 1; o <= 2; o <<= 1) {
                rs_[t] += __shfl_xor_sync(0xffffffffu, rs_[t], o);
                rq_[t] += __shfl_xor_sync(0xffffffffu, rq_[t], o);
            }
        if ((lane & 3) == 0) {
#pragma unroll
            for (int i = 0; i < 2; i++)
#pragma unroll
                for (int h = 0; h < 2; h++) {
                    int rloc = warp_m * 32 + i * 16 + h * 8 + (lane >> 2);
                    red_s[rloc * 4 + warp_n] = rs_[i * 2 + h];
                    red_q[rloc * 4 + warp_n] = rq_[i * 2 + h];
                }
        }
        __syncthreads();
#pragma unroll
        for (int i = 0; i < 2; i++)
#pragma unroll
            for (int h = 0; h < 2; h++) {
                int rloc = warp_m * 32 + i * 16 + h * 8 + (lane >> 2);
                float s = red_s[rloc * 4 + 0] + red_s[rloc * 4 + 1]
                        + red_s[rloc * 4 + 2] + red_s[rloc * 4 + 3];
                float q = red_q[rloc * 4 + 0] + red_q[rloc * 4 + 1]
                        + red_q[rloc * 4 + 2] + red_q[rloc * 4 + 3];
                float mu = s * (1.f / 256.f);
                float rinv = rsqrtf(q * (1.f / 256.f) - mu * mu + 1e-5f);
#pragma unroll
                for (int j = 0; j < 8; j++) {
                    int col = warp_n * 64 + j * 8 + (lane & 3) * 2;
                    float y0 = round_tf32((hreg[i * 8 + j][h * 2 + 0] - mu) * rinv * gam[col]     + bet[col]);
                    float y1 = round_tf32((hreg[i * 8 + j][h * 2 + 1] - mu) * rinv * gam[col + 1] + bet[col + 1]);
                    int cc = col & 31, kb = col >> 5;
                    uint32_t addr = LNB + (uint32_t)(kb * 16384 + rloc * 128
                                   + (((cc >> 2) ^ (rloc & 7)) << 4) + (cc & 3) * 4);
                    st2s(addr, y0, y1);
                }
            }
        __syncthreads();
    };

    // prefetch first W1 slice of layer 0
    issueW1(g_W1p);

    // ================= 8 residual layers =================
#pragma unroll 1
    for (int l = 0; l < 8; l++) {
        do_ln(lng + l * 256, lnbet + l * 256);
        const float* W1 = g_W1p + (size_t)l * 8 * 512 * 32;
        const float* W2 = g_W2p + (size_t)l * 16 * 256 * 32;
        const float* b1 = b1g + l * 512;
#pragma unroll 1
        for (int kc = 0; kc < 16; kc++) {
            issueW2(W2 + (size_t)kc * 8192);
            CPA_WAIT(1);                     // W1(kc) ready; W2(kc) in flight
            __syncthreads();
            // ---- GEMM1: tchunk(128x32) = ln(128x256) @ W1slice ----
            float a1[2][4] = {};
#pragma unroll
            for (int kb = 0; kb < 8; kb++) {
#pragma unroll
                for (int s = 0; s < 4; s++) {
                    int g = s * 2 + lg;
                    uint32_t af[4];
                    int R = wm1 * 16 + lr + lh * 8;
                    ldm4(af, LNB + (uint32_t)(kb * 16384 + R * 128 + ((g ^ (R & 7)) << 4)));
                    int n = wn1 * 16 + lr + lh * 8;
                    uint32_t t4[4];
                    ldm4(t4, WBa + (uint32_t)(kb * 4096 + n * 128 + ((g ^ (n & 7)) << 4)));
                    mma_tf32(a1[0], af, t4[0], t4[2]);
                    mma_tf32(a1[1], af, t4[1], t4[3]);
                }
            }
            // ---- relu + bias + round -> tchunk smem ----
#pragma unroll
            for (int f = 0; f < 2; f++) {
                int row0 = wm1 * 16 + (lane >> 2);
                int colL = wn1 * 16 + f * 8 + (lane & 3) * 2;
                int gc = kc * 32 + colL;
                float bb0 = b1[gc], bb1 = b1[gc + 1];
                float t0 = round_tf32(fmaxf(a1[f][0] + bb0, 0.f));
                float t1 = round_tf32(fmaxf(a1[f][1] + bb1, 0.f));
                float t2 = round_tf32(fmaxf(a1[f][2] + bb0, 0.f));
                float t3 = round_tf32(fmaxf(a1[f][3] + bb1, 0.f));
                uint32_t sw = (uint32_t)((((colL >> 2) ^ (row0 & 7)) << 4) + (colL & 3) * 4);
                st2s(TCH + (uint32_t)(row0 * 128) + sw, t0, t1);
                st2s(TCH + (uint32_t)((row0 + 8) * 128) + sw, t2, t3);
            }
            __syncthreads();                 // TCH visible; WBa free
            // ---- prefetch next W1 slice ----
            if (kc < 15)      issueW1(W1 + (size_t)(kc + 1) * 32 * 32);
            else if (l < 7)   issueW1(g_W1p + (size_t)(l + 1) * 8 * 512 * 32);
            if (l == 7 && kc == 15) { CPA_WAIT(0); } else { CPA_WAIT(1); }  // W2(kc) ready
            __syncthreads();
            // ---- GEMM2: hreg += tchunk(128x32) @ W2chunk(32x256) ----
#pragma unroll
            for (int s = 0; s < 4; s++) {
                int g = s * 2 + lg;
                uint32_t af[2][4];
#pragma unroll
                for (int i = 0; i < 2; i++) {
                    int R = warp_m * 32 + i * 16 + lr + lh * 8;
                    ldm4(af[i], TCH + (uint32_t)(R * 128 + ((g ^ (R & 7)) << 4)));
                }
                uint32_t bf[8][2];
#pragma unroll
                for (int p = 0; p < 4; p++) {
                    int n = warp_n * 64 + p * 16 + lr + lh * 8;
                    uint32_t t4[4];
                    ldm4(t4, WBb + (uint32_t)(n * 128 + ((g ^ (n & 7)) << 4)));
                    bf[2 * p][0] = t4[0]; bf[2 * p + 1][0] = t4[1];
                    bf[2 * p][1] = t4[2]; bf[2 * p + 1][1] = t4[3];
                }
#pragma unroll
                for (int i = 0; i < 2; i++)
#pragma unroll
                    for (int j = 0; j < 8; j++)
                        mma_tf32(hreg[i * 8 + j], af[i], bf[j][0], bf[j][1]);
            }
            __syncthreads();                 // WBb free
        }
        const float* b2 = b2g + l * 256;
#pragma unroll
        for (int i = 0; i < 2; i++)
#pragma unroll
            for (int j = 0; j < 8; j++) {
                int col = warp_n * 64 + j * 8 + (lane & 3) * 2;
                float b0 = b2[col], b1v = b2[col + 1];
                hreg[i * 8 + j][0] += b0;  hreg[i * 8 + j][1] += b1v;
                hreg[i * 8 + j][2] += b0;  hreg[i * 8 + j][3] += b1v;
            }
    }

    // ================= final LN + head =================
    {
        float rs_[4] = {0.f, 0.f, 0.f, 0.f}, rq_[4] = {0.f, 0.f, 0.f, 0.f};
#pragma unroll
        for (int i = 0; i < 2; i++)
#pragma unroll
            for (int j = 0; j < 8; j++) {
                float v0 = hreg[i * 8 + j][0], v1 = hreg[i * 8 + j][1];
                float v2 = hreg[i * 8 + j][2], v3 = hreg[i * 8 + j][3];
                rs_[i * 2 + 0] += v0 + v1;  rq_[i * 2 + 0] += v0 * v0 + v1 * v1;
                rs_[i * 2 + 1] += v2 + v3;  rq_[i * 2 + 1] += v2 * v2 + v3 * v3;
            }
#pragma unroll
        for (int t = 0; t < 4; t++)
#pragma unroll
            for (int o = 1; o <= 2; o <<= 1) {
                rs_[t] += __shfl_xor_sync(0xffffffffu, rs_[t], o);
                rq_[t] += __shfl_xor_sync(0xffffffffu, rq_[t], o);
            }
        if ((lane & 3) == 0) {
#pragma unroll
            for (int i = 0; i < 2; i++)
#pragma unroll
                for (int h = 0; h < 2; h++) {
                    int rloc = warp_m * 32 + i * 16 + h * 8 + (lane >> 2);
                    red_s[rloc * 4 + warp_n] = rs_[i * 2 + h];
                    red_q[rloc * 4 + warp_n] = rq_[i * 2 + h];
                }
        }
        __syncthreads();
        float hd0[4] = {0.f, 0.f, 0.f, 0.f}, hd1[4] = {0.f, 0.f, 0.f, 0.f};
#pragma unroll
        for (int i = 0; i < 2; i++)
#pragma unroll
            for (int h = 0; h < 2; h++) {
                int rloc = warp_m * 32 + i * 16 + h * 8 + (lane >> 2);
                float s = red_s[rloc * 4 + 0] + red_s[rloc * 4 + 1]
                        + red_s[rloc * 4 + 2] + red_s[rloc * 4 + 3];
                float q = red_q[rloc * 4 + 0] + red_q[rloc * 4 + 1]
                        + red_q[rloc * 4 + 2] + red_q[rloc * 4 + 3];
                float mu = s * (1.f / 256.f);
                float rinv = rsqrtf(q * (1.f / 256.f) - mu * mu + 1e-5f);
#pragma unroll
                for (int j = 0; j < 8; j++) {
                    int col = warp_n * 64 + j * 8 + (lane & 3) * 2;
                    float y0 = (hreg[i * 8 + j][h * 2 + 0] - mu) * rinv * gf[col]     + betf[col];
                    float y1 = (hreg[i * 8 + j][h * 2 + 1] - mu) * rinv * gf[col + 1] + betf[col + 1];
                    hd0[i * 2 + h] += y0 * Wh[col * 2 + 0] + y1 * Wh[col * 2 + 2];
                    hd1[i * 2 + h] += y0 * Wh[col * 2 + 1] + y1 * Wh[col * 2 + 3];
                }
            }
#pragma unroll
        for (int t = 0; t < 4; t++)
#pragma unroll
            for (int o = 1; o <= 2; o <<= 1) {
                hd0[t] += __shfl_xor_sync(0xffffffffu, hd0[t], o);
                hd1[t] += __shfl_xor_sync(0xffffffffu, hd1[t], o);
            }
        __syncthreads();
        if ((lane & 3) == 0) {
#pragma unroll
            for (int i = 0; i < 2; i++)
#pragma unroll
                for (int h = 0; h < 2; h++) {
                    int rloc = warp_m * 32 + i * 16 + h * 8 + (lane >> 2);
                    red_s[rloc * 4 + warp_n] = hd0[i * 2 + h];
                    red_q[rloc * 4 + warp_n] = hd1[i * 2 + h];
                }
        }
        __syncthreads();
        if (tid < 128) {
            float s0 = red_s[tid * 4 + 0] + red_s[tid * 4 + 1]
                     + red_s[tid * 4 + 2] + red_s[tid * 4 + 3];
            float s1 = red_q[tid * 4 + 0] + red_q[tid * 4 + 1]
                     + red_q[tid * 4 + 2] + red_q[tid * 4 + 3];
            out[(bm + tid) * 2 + 0] = s0 + bh[0];
            out[(bm + tid) * 2 + 1] = s1 + bh[1];
        }
    }
}

// ---------------- launch ----------------
extern "C" void kernel_launch(void* const* d_in, const int* in_sizes, int n_in,
                              void* d_out, int out_size) {
    const float* x_num   = (const float*)d_in[0];
    const int*   xidx    = (const int*)  d_in[1];
    const float* w_num   = (const float*)d_in[2];
    const float* b_num   = (const float*)d_in[3];
    const float* cat_emb = (const float*)d_in[4];
    const float* W_first = (const float*)d_in[5];
    const float* b_first = (const float*)d_in[6];
    const float* ln_g    = (const float*)d_in[7];
    const float* ln_b    = (const float*)d_in[8];
    const float* W1s     = (const float*)d_in[9];
    const float* b1s     = (const float*)d_in[10];
    const float* W2s     = (const float*)d_in[11];
    const float* b2s     = (const float*)d_in[12];
    const float* g_f     = (const float*)d_in[13];
    const float* beta_f  = (const float*)d_in[14];
    const float* W_head  = (const float*)d_in[15];
    const float* b_head  = (const float*)d_in[16];

    cudaFuncSetAttribute(fused_net, cudaFuncAttributeMaxDynamicSharedMemorySize, SMEM_DYN);

    float* g_Anum_p; cudaGetSymbolAddress((void**)&g_Anum_p, g_Anum);
    float* g_W1p_p;  cudaGetSymbolAddress((void**)&g_W1p_p,  g_W1p);
    float* g_W2p_p;  cudaGetSymbolAddress((void**)&g_W2p_p,  g_W2p);
    float* g_Wfp_p;  cudaGetSymbolAddress((void**)&g_Wfp_p,  g_Wfp);

    prep_anum<<<32, 256>>>(w_num, W_first);
    prep_c1<<<32, 256>>>(b_num, W_first);
    prep_c2<<<1, 256>>>(b_first);
    pack_w<<<2048, 256>>>(W1s, g_W1p_p, 8 * 256, 512);
    pack_w<<<2048, 256>>>(W2s, g_W2p_p, 8 * 512, 256);
    pack_w<<<64,   256>>>(g_Anum_p, g_Wfp_p, 32, 256);
    pack_w<<<2048, 256>>>(W_first + (size_t)8192 * 256, g_Wfp_p + 8192, 4096, 256);

    fused_net<<<128, 512, SMEM_DYN>>>(
        x_num, xidx, cat_emb, b1s, b2s, ln_g, ln_b,
        g_f, beta_f, W_head, b_head, (float*)d_out);
}

// round 8
// speedup vs baseline: 1.0718x; 1.0718x over previous
#include <cuda_runtime.h>
#include <cstdint>

// ---------------- problem constants ----------------
static constexpr int Bsz = 16384;
static constexpr int SMEM_DYN = 104 * 1024 + 1024;   // ln 64K + tchunk 8K + wbuf 32K (+align)

// ---------------- device scratch ----------------
__device__ float g_Anum[32 * 256];
__device__ float g_c[256];
__device__ float g_cpart[32 * 256];
__device__ float g_W1p[8 * 8  * 512 * 32];   // [l][kb][n(512)][32] swizzled tf32
__device__ float g_W2p[8 * 16 * 256 * 32];   // [l][kb][n(256)][32] swizzled tf32
__device__ float g_Wfp[129 * 256 * 32];      // first-layer packed (kb0 = folded numeric)

// ---------------- PTX helpers ----------------
__device__ __forceinline__ uint32_t sm32(const void* p) {
    uint32_t a;
    asm("{ .reg .u64 t; cvta.to.shared.u64 t, %1; cvt.u32.u64 %0, t; }" : "=r"(a) : "l"(p));
    return a;
}
__device__ __forceinline__ void cpa16(uint32_t dst, const void* src) {
    asm volatile("cp.async.cg.shared.global [%0], [%1], 16;" :: "r"(dst), "l"(src));
}
#define CPA_COMMIT() asm volatile("cp.async.commit_group;" ::: "memory")
#define CPA_WAIT(n)  asm volatile("cp.async.wait_group %0;" :: "n"(n) : "memory")

__device__ __forceinline__ void ldm4(uint32_t (&r)[4], uint32_t addr) {
    asm volatile("ldmatrix.sync.aligned.m8n8.x4.shared.b16 {%0,%1,%2,%3}, [%4];"
                 : "=r"(r[0]), "=r"(r[1]), "=r"(r[2]), "=r"(r[3]) : "r"(addr));
}
__device__ __forceinline__ uint32_t to_tf32(uint32_t v) {
    uint32_t o;
    asm("cvt.rna.tf32.f32 %0, %1;" : "=r"(o) : "f"(__uint_as_float(v)));
    return o;
}
__device__ __forceinline__ float round_tf32(float v) {
    uint32_t o;
    asm("cvt.rna.tf32.f32 %0, %1;" : "=r"(o) : "f"(v));
    return __uint_as_float(o);
}
__device__ __forceinline__ void mma_tf32(float (&d)[4], const uint32_t (&a)[4],
                                         uint32_t b0, uint32_t b1) {
    asm volatile("mma.sync.aligned.m16n8k8.row.col.f32.tf32.tf32.f32 "
                 "{%0,%1,%2,%3}, {%4,%5,%6,%7}, {%8,%9}, {%0,%1,%2,%3};"
                 : "+f"(d[0]), "+f"(d[1]), "+f"(d[2]), "+f"(d[3])
                 : "r"(a[0]), "r"(a[1]), "r"(a[2]), "r"(a[3]), "r"(b0), "r"(b1));
}
__device__ __forceinline__ void st2s(uint32_t addr, float x, float y) {
    asm volatile("st.shared.v2.f32 [%0], {%1, %2};" :: "r"(addr), "f"(x), "f"(y));
}

// ---------------- prep kernels ----------------
__global__ void prep_anum(const float* __restrict__ w_num, const float* __restrict__ W_first) {
    int f = blockIdx.x, j = threadIdx.x;
    const float* Wf = W_first + (size_t)f * 256 * 256 + j;
    const float* wn = w_num + f * 256;
    float acc = 0.f;
    for (int d = 0; d < 256; d++) acc = fmaf(wn[d], Wf[(size_t)d * 256], acc);
    g_Anum[f * 256 + j] = acc;
}
__global__ void prep_c1(const float* __restrict__ b_num, const float* __restrict__ W_first) {
    int b = blockIdx.x, j = threadIdx.x;
    float acc = 0.f;
    const float* W = W_first + (size_t)b * 256 * 256 + j;
    const float* bn = b_num + b * 256;
    for (int k = 0; k < 256; k++) acc = fmaf(bn[k], W[(size_t)k * 256], acc);
    g_cpart[b * 256 + j] = acc;
}
__global__ void prep_c2(const float* __restrict__ b_first) {
    int j = threadIdx.x;
    float acc = b_first[j];
    for (int b = 0; b < 32; b++) acc += g_cpart[b * 256 + j];
    g_c[j] = acc;
}
__global__ void pack_w(const float* __restrict__ src, float* __restrict__ dst, int Ktot, int N) {
    int total = (Ktot / 32) * N * 32;
    for (int i = blockIdx.x * blockDim.x + threadIdx.x; i < total; i += gridDim.x * blockDim.x) {
        int j  = i & 31;
        int n  = (i >> 5) % N;
        int kb = i / (N * 32);
        int k  = (((j >> 2) ^ (n & 7)) << 2) | (j & 3);
        dst[i] = round_tf32(src[(size_t)(kb * 32 + k) * N + n]);
    }
}

// =====================================================================
// Persistent fused network kernel. One CTA = 64 rows, 256 threads, occ 2.
// Weight loads split into 16KB halves (B0/B1); each load overlaps one
// compute stage. Residual stream h lives in registers.
// =====================================================================
__global__ __launch_bounds__(256, 2) void fused_net(
    const float* __restrict__ xnum, const int* __restrict__ xidx,
    const float* __restrict__ cemb,
    const float* __restrict__ b1g, const float* __restrict__ b2g,
    const float* __restrict__ lng, const float* __restrict__ lnbet,
    const float* __restrict__ gf,  const float* __restrict__ betf,
    const float* __restrict__ Wh,  const float* __restrict__ bh,
    float* __restrict__ out)
{
    extern __shared__ float dsm[];
    __shared__ float red_s[64 * 4], red_q[64 * 4];
    uint32_t raw  = sm32(dsm);
    uint32_t base = (raw + 1023u) & ~1023u;
    const uint32_t LNB = base;            // 64 KB: ln tile, 8 chunks of (64r x 32k)
    const uint32_t TCH = base + 65536u;   //  8 KB: t chunk (64r x 32k)
    const uint32_t B0  = base + 73728u;   // 16 KB weight half-buffer
    const uint32_t B1  = base + 90112u;   // 16 KB weight half-buffer

    int tid = threadIdx.x, wid = tid >> 5, lane = tid & 31;
    int bm = blockIdx.x * 64;
    int warp_m = wid & 1, warp_n = wid >> 1;   // GEMM2 / phase0: 2 x 4 (64 x 256)
    int wm1 = wid & 3,    wn1 = wid >> 2;      // GEMM1: 4 x 2 (64 x 32)
    int lr = lane & 7, lh = (lane >> 3) & 1, lg = lane >> 4;

    float hreg[16][4];
#pragma unroll
    for (int t = 0; t < 16; t++)
#pragma unroll
        for (int q = 0; q < 4; q++) hreg[t][q] = 0.f;

    // ================= Phase 0: first GEMM (gathered A, K=4128) ==========
    {
        int ar = tid >> 2, aq = tid & 3, m = bm + ar;
        auto issue = [&](int c, int b) {
            const float* arow;
            if (c == 0) arow = xnum + (size_t)m * 32;
            else {
                int cc = c - 1, f = cc >> 3, d0 = (cc & 7) << 5;
                arow = cemb + (size_t)xidx[m * 16 + f] * 256 + d0;
            }
            uint32_t Ad = base + (uint32_t)b * 8192u + (uint32_t)ar * 128u;
#pragma unroll
            for (int i = 0; i < 2; i++) {
                int g = aq + i * 4;
                cpa16(Ad + (uint32_t)((g ^ (ar & 7)) << 4), arow + g * 4);
            }
            const float4* bsrc = (const float4*)(g_Wfp + (size_t)c * 8192) + tid;
            uint32_t Bd = base + 16384u + (uint32_t)b * 32768u + (uint32_t)tid * 16u;
#pragma unroll
            for (int i = 0; i < 8; i++) cpa16(Bd + (uint32_t)i * 4096u, bsrc + i * 256);
            CPA_COMMIT();
        };
        issue(0, 0);
        issue(1, 1);
#pragma unroll 1
        for (int c = 0; c < 129; c++) {
            if (c + 1 < 129) CPA_WAIT(1); else CPA_WAIT(0);
            __syncthreads();
            uint32_t Ab = base + (uint32_t)(c & 1) * 8192u;
            uint32_t Bb = base + 16384u + (uint32_t)(c & 1) * 32768u;
#pragma unroll
            for (int s = 0; s < 4; s++) {
                uint32_t af[2][4];
#pragma unroll
                for (int i = 0; i < 2; i++) {
                    int R = warp_m * 32 + i * 16 + lr + lh * 8;
                    int g = s * 2 + lg;
                    ldm4(af[i], Ab + (uint32_t)(R * 128 + ((g ^ (R & 7)) << 4)));
#pragma unroll
                    for (int q = 0; q < 4; q++) af[i][q] = to_tf32(af[i][q]);
                }
                uint32_t bf[8][2];
#pragma unroll
                for (int p = 0; p < 4; p++) {
                    int n = warp_n * 64 + p * 16 + lr + lh * 8;
                    int g = s * 2 + lg;
                    uint32_t t4[4];
                    ldm4(t4, Bb + (uint32_t)(n * 128 + ((g ^ (n & 7)) << 4)));
                    bf[2 * p][0] = t4[0]; bf[2 * p + 1][0] = t4[1];
                    bf[2 * p][1] = t4[2]; bf[2 * p + 1][1] = t4[3];
                }
#pragma unroll
                for (int i = 0; i < 2; i++)
#pragma unroll
                    for (int j = 0; j < 8; j++)
                        mma_tf32(hreg[i * 8 + j], af[i], bf[j][0], bf[j][1]);
            }
            __syncthreads();
            if (c + 2 < 129) issue(c + 2, c & 1);
        }
        // folded bias
#pragma unroll
        for (int i = 0; i < 2; i++)
#pragma unroll
            for (int j = 0; j < 8; j++) {
                int col = warp_n * 64 + j * 8 + (lane & 3) * 2;
                float b0 = g_c[col], b1 = g_c[col + 1];
                hreg[i * 8 + j][0] += b0; hreg[i * 8 + j][1] += b1;
                hreg[i * 8 + j][2] += b0; hreg[i * 8 + j][3] += b1;
            }
    }

    // ---- half-size weight loaders (16KB each, one commit group per call) ----
    // W1 half: kb pieces [half*4 .. half*4+3], each 32n x 32k (4KB)
    auto issueW1h = [&](const float* W1, int kc, int half, uint32_t B) {
#pragma unroll
        for (int i = 0; i < 4; i++) {
            int kb = half * 4 + i;
            cpa16(B + (uint32_t)(i * 4096 + tid * 16),
                  W1 + ((size_t)kb * 512 + kc * 32) * 32 + tid * 4);
        }
        CPA_COMMIT();
    };
    // W2 half: pieces {2e+half}, e=0..3; piece = 32n x 32k (4KB)
    auto issueW2h = [&](const float* W2, int kc, int half, uint32_t B) {
        const float* src = W2 + (size_t)kc * 8192;
#pragma unroll
        for (int i = 0; i < 4; i++) {
            int pg = 2 * i + half;
            cpa16(B + (uint32_t)(i * 4096 + tid * 16), src + pg * 1024 + tid * 4);
        }
        CPA_COMMIT();
    };

    // ---- LN from hreg -> ln smem (tf32-rounded) ----
    auto do_ln = [&](const float* gam, const float* bet) {
        float rs_[4] = {0.f, 0.f, 0.f, 0.f}, rq_[4] = {0.f, 0.f, 0.f, 0.f};
#pragma unroll
        for (int i = 0; i < 2; i++)
#pragma unroll
            for (int j = 0; j < 8; j++) {
                float v0 = hreg[i * 8 + j][0], v1 = hreg[i * 8 + j][1];
                float v2 = hreg[i * 8 + j][2], v3 = hreg[i * 8 + j][3];
                rs_[i * 2 + 0] += v0 + v1;  rq_[i * 2 + 0] += v0 * v0 + v1 * v1;
                rs_[i * 2 + 1] += v2 + v3;  rq_[i * 2 + 1] += v2 * v2 + v3 * v3;
            }
#pragma unroll
        for (int t = 0; t < 4; t++)
#pragma unroll
            for (int o = 1; o <= 2; o <<= 1) {
                rs_[t] += __shfl_xor_sync(0xffffffffu, rs_[t], o);
                rq_[t] += __shfl_xor_sync(0xffffffffu, rq_[t], o);
            }
        if ((lane & 3) == 0) {
#pragma unroll
            for (int i = 0; i < 2; i++)
#pragma unroll
                for (int h = 0; h < 2; h++) {
                    int rloc = warp_m * 32 + i * 16 + h * 8 + (lane >> 2);
                    red_s[rloc * 4 + warp_n] = rs_[i * 2 + h];
                    red_q[rloc * 4 + warp_n] = rq_[i * 2 + h];
                }
        }
        __syncthreads();
#pragma unroll
        for (int i = 0; i < 2; i++)
#pragma unroll
            for (int h = 0; h < 2; h++) {
                int rloc = warp_m * 32 + i * 16 + h * 8 + (lane >> 2);
                float s = red_s[rloc * 4 + 0] + red_s[rloc * 4 + 1]
                        + red_s[rloc * 4 + 2] + red_s[rloc * 4 + 3];
                float q = red_q[rloc * 4 + 0] + red_q[rloc * 4 + 1]
                        + red_q[rloc * 4 + 2] + red_q[rloc * 4 + 3];
                float mu = s * (1.f / 256.f);
                float rinv = rsqrtf(q * (1.f / 256.f) - mu * mu + 1e-5f);
#pragma unroll
                for (int j = 0; j < 8; j++) {
                    int col = warp_n * 64 + j * 8 + (lane & 3) * 2;
                    float y0 = round_tf32((hreg[i * 8 + j][h * 2 + 0] - mu) * rinv * gam[col]     + bet[col]);
                    float y1 = round_tf32((hreg[i * 8 + j][h * 2 + 1] - mu) * rinv * gam[col + 1] + bet[col + 1]);
                    int cc = col & 31, kb = col >> 5;
                    uint32_t addr = LNB + (uint32_t)(kb * 8192 + rloc * 128
                                   + (((cc >> 2) ^ (rloc & 7)) << 4) + (cc & 3) * 4);
                    st2s(addr, y0, y1);
                }
            }
        __syncthreads();
    };

    // GEMM2 half: warp's piece lives at B + warp_n*4096
    auto g2half = [&](uint32_t B, int half) {
#pragma unroll
        for (int s = 0; s < 4; s++) {
            int g = s * 2 + lg;
            uint32_t af[2][4];
#pragma unroll
            for (int i = 0; i < 2; i++) {
                int R = warp_m * 32 + i * 16 + lr + lh * 8;
                ldm4(af[i], TCH + (uint32_t)(R * 128 + ((g ^ (R & 7)) << 4)));
            }
            uint32_t bf[4][2];
#pragma unroll
            for (int pp = 0; pp < 2; pp++) {
                int nloc = pp * 16 + lr + lh * 8;
                uint32_t t4[4];
                ldm4(t4, B + (uint32_t)(warp_n * 4096 + nloc * 128 + ((g ^ (nloc & 7)) << 4)));
                bf[2 * pp][0] = t4[0]; bf[2 * pp + 1][0] = t4[1];
                bf[2 * pp][1] = t4[2]; bf[2 * pp + 1][1] = t4[3];
            }
#pragma unroll
            for (int i = 0; i < 2; i++)
#pragma unroll
                for (int jj = 0; jj < 4; jj++)
                    mma_tf32(hreg[i * 8 + half * 4 + jj], af[i], bf[jj][0], bf[jj][1]);
        }
    };

    // prologue: W1 half0 of layer 0, kc 0 -> B0
    issueW1h(g_W1p, 0, 0, B0);

    // ================= 8 residual layers =================
#pragma unroll 1
    for (int l = 0; l < 8; l++) {
        do_ln(lng + l * 256, lnbet + l * 256);
        const float* W1 = g_W1p + (size_t)l * 8 * 512 * 32;
        const float* W2 = g_W2p + (size_t)l * 16 * 256 * 32;
        const float* b1 = b1g + l * 512;
#pragma unroll 1
        for (int kc = 0; kc < 16; kc++) {
            float a1[2][4] = {};
            // ---- S1: wait W1a; B1 free (post-G2b) -> issue W1b; GEMM1 kb0-3 ----
            CPA_WAIT(0);
            __syncthreads();
            issueW1h(W1, kc, 1, B1);
#pragma unroll
            for (int kb = 0; kb < 4; kb++) {
#pragma unroll
                for (int s = 0; s < 4; s++) {
                    int g = s * 2 + lg;
                    uint32_t af[4];
                    int R = wm1 * 16 + lr + lh * 8;
                    ldm4(af, LNB + (uint32_t)(kb * 8192 + R * 128 + ((g ^ (R & 7)) << 4)));
                    int n = wn1 * 16 + lr + lh * 8;
                    uint32_t t4[4];
                    ldm4(t4, B0 + (uint32_t)(kb * 4096 + n * 128 + ((g ^ (n & 7)) << 4)));
                    mma_tf32(a1[0], af, t4[0], t4[2]);
                    mma_tf32(a1[1], af, t4[1], t4[3]);
                }
            }
            // ---- S2: wait W1b; B0 free (post-G1a) -> issue W2even; GEMM1 kb4-7; TCH ----
            CPA_WAIT(0);
            __syncthreads();
            issueW2h(W2, kc, 0, B0);
#pragma unroll
            for (int kb = 4; kb < 8; kb++) {
#pragma unroll
                for (int s = 0; s < 4; s++) {
                    int g = s * 2 + lg;
                    uint32_t af[4];
                    int R = wm1 * 16 + lr + lh * 8;
                    ldm4(af, LNB + (uint32_t)(kb * 8192 + R * 128 + ((g ^ (R & 7)) << 4)));
                    int n = wn1 * 16 + lr + lh * 8;
                    uint32_t t4[4];
                    ldm4(t4, B1 + (uint32_t)((kb - 4) * 4096 + n * 128 + ((g ^ (n & 7)) << 4)));
                    mma_tf32(a1[0], af, t4[0], t4[2]);
                    mma_tf32(a1[1], af, t4[1], t4[3]);
                }
            }
#pragma unroll
            for (int f = 0; f < 2; f++) {
                int row0 = wm1 * 16 + (lane >> 2);
                int colL = wn1 * 16 + f * 8 + (lane & 3) * 2;
                int gc = kc * 32 + colL;
                float bb0 = b1[gc], bb1 = b1[gc + 1];
                float t0 = round_tf32(fmaxf(a1[f][0] + bb0, 0.f));
                float t1 = round_tf32(fmaxf(a1[f][1] + bb1, 0.f));
                float t2 = round_tf32(fmaxf(a1[f][2] + bb0, 0.f));
                float t3 = round_tf32(fmaxf(a1[f][3] + bb1, 0.f));
                uint32_t sw = (uint32_t)((((colL >> 2) ^ (row0 & 7)) << 4) + (colL & 3) * 4);
                st2s(TCH + (uint32_t)(row0 * 128) + sw, t0, t1);
                st2s(TCH + (uint32_t)((row0 + 8) * 128) + sw, t2, t3);
            }
            // ---- S3: wait W2even; B1 free (post-G1b), TCH visible -> issue W2odd; GEMM2 even ----
            CPA_WAIT(0);
            __syncthreads();
            issueW2h(W2, kc, 1, B1);
            g2half(B0, 0);
            // ---- S4: wait W2odd; B0 free (post-G2a) -> issue next W1a; GEMM2 odd ----
            CPA_WAIT(0);
            __syncthreads();
            if (kc < 15)    issueW1h(W1, kc + 1, 0, B0);
            else if (l < 7) issueW1h(g_W1p + (size_t)(l + 1) * 8 * 512 * 32, 0, 0, B0);
            g2half(B1, 1);
        }
        // ---- b2 bias ----
        const float* b2 = b2g + l * 256;
#pragma unroll
        for (int i = 0; i < 2; i++)
#pragma unroll
            for (int j = 0; j < 8; j++) {
                int col = warp_n * 64 + j * 8 + (lane & 3) * 2;
                float b0 = b2[col], b1v = b2[col + 1];
                hreg[i * 8 + j][0] += b0;  hreg[i * 8 + j][1] += b1v;
                hreg[i * 8 + j][2] += b0;  hreg[i * 8 + j][3] += b1v;
            }
    }

    // ================= final LN + head =================
    {
        float rs_[4] = {0.f, 0.f, 0.f, 0.f}, rq_[4] = {0.f, 0.f, 0.f, 0.f};
#pragma unroll
        for (int i = 0; i < 2; i++)
#pragma unroll
            for (int j = 0; j < 8; j++) {
                float v0 = hreg[i * 8 + j][0], v1 = hreg[i * 8 + j][1];
                float v2 = hreg[i * 8 + j][2], v3 = hreg[i * 8 + j][3];
                rs_[i * 2 + 0] += v0 + v1;  rq_[i * 2 + 0] += v0 * v0 + v1 * v1;
                rs_[i * 2 + 1] += v2 + v3;  rq_[i * 2 + 1] += v2 * v2 + v3 * v3;
            }
#pragma unroll
        for (int t = 0; t < 4; t++)
#pragma unroll
            for (int o = 1; o <= 2; o <<= 1) {
                rs_[t] += __shfl_xor_sync(0xffffffffu, rs_[t], o);
                rq_[t] += __shfl_xor_sync(0xffffffffu, rq_[t], o);
            }
        if ((lane & 3) == 0) {
#pragma unroll
            for (int i = 0; i < 2; i++)
#pragma unroll
                for (int h = 0; h < 2; h++) {
                    int rloc = warp_m * 32 + i * 16 + h * 8 + (lane >> 2);
                    red_s[rloc * 4 + warp_n] = rs_[i * 2 + h];
                    red_q[rloc * 4 + warp_n] = rq_[i * 2 + h];
                }
        }
        __syncthreads();
        float hd0[4] = {0.f, 0.f, 0.f, 0.f}, hd1[4] = {0.f, 0.f, 0.f, 0.f};
#pragma unroll
        for (int i = 0; i < 2; i++)
#pragma unroll
            for (int h = 0; h < 2; h++) {
                int rloc = warp_m * 32 + i * 16 + h * 8 + (lane >> 2);
                float s = red_s[rloc * 4 + 0] + red_s[rloc * 4 + 1]
                        + red_s[rloc * 4 + 2] + red_s[rloc * 4 + 3];
                float q = red_q[rloc * 4 + 0] + red_q[rloc * 4 + 1]
                        + red_q[rloc * 4 + 2] + red_q[rloc * 4 + 3];
                float mu = s * (1.f / 256.f);
                float rinv = rsqrtf(q * (1.f / 256.f) - mu * mu + 1e-5f);
#pragma unroll
                for (int j = 0; j < 8; j++) {
                    int col = warp_n * 64 + j * 8 + (lane & 3) * 2;
                    float y0 = (hreg[i * 8 + j][h * 2 + 0] - mu) * rinv * gf[col]     + betf[col];
                    float y1 = (hreg[i * 8 + j][h * 2 + 1] - mu) * rinv * gf[col + 1] + betf[col + 1];
                    hd0[i * 2 + h] += y0 * Wh[col * 2 + 0] + y1 * Wh[col * 2 + 2];
                    hd1[i * 2 + h] += y0 * Wh[col * 2 + 1] + y1 * Wh[col * 2 + 3];
                }
            }
#pragma unroll
        for (int t = 0; t < 4; t++)
#pragma unroll
            for (int o = 1; o <= 2; o <<= 1) {
                hd0[t] += __shfl_xor_sync(0xffffffffu, hd0[t], o);
                hd1[t] += __shfl_xor_sync(0xffffffffu, hd1[t], o);
            }
        __syncthreads();
        if ((lane & 3) == 0) {
#pragma unroll
            for (int i = 0; i < 2; i++)
#pragma unroll
                for (int h = 0; h < 2; h++) {
                    int rloc = warp_m * 32 + i * 16 + h * 8 + (lane >> 2);
                    red_s[rloc * 4 + warp_n] = hd0[i * 2 + h];
                    red_q[rloc * 4 + warp_n] = hd1[i * 2 + h];
                }
        }
        __syncthreads();
        if (tid < 64) {
            float s0 = red_s[tid * 4 + 0] + red_s[tid * 4 + 1]
                     + red_s[tid * 4 + 2] + red_s[tid * 4 + 3];
            float s1 = red_q[tid * 4 + 0] + red_q[tid * 4 + 1]
                     + red_q[tid * 4 + 2] + red_q[tid * 4 + 3];
            out[(bm + tid) * 2 + 0] = s0 + bh[0];
            out[(bm + tid) * 2 + 1] = s1 + bh[1];
        }
    }
}

// ---------------- launch ----------------
extern "C" void kernel_launch(void* const* d_in, const int* in_sizes, int n_in,
                              void* d_out, int out_size) {
    const float* x_num   = (const float*)d_in[0];
    const int*   xidx    = (const int*)  d_in[1];
    const float* w_num   = (const float*)d_in[2];
    const float* b_num   = (const float*)d_in[3];
    const float* cat_emb = (const float*)d_in[4];
    const float* W_first = (const float*)d_in[5];
    const float* b_first = (const float*)d_in[6];
    const float* ln_g    = (const float*)d_in[7];
    const float* ln_b    = (const float*)d_in[8];
    const float* W1s     = (const float*)d_in[9];
    const float* b1s     = (const float*)d_in[10];
    const float* W2s     = (const float*)d_in[11];
    const float* b2s     = (const float*)d_in[12];
    const float* g_f     = (const float*)d_in[13];
    const float* beta_f  = (const float*)d_in[14];
    const float* W_head  = (const float*)d_in[15];
    const float* b_head  = (const float*)d_in[16];

    cudaFuncSetAttribute(fused_net, cudaFuncAttributeMaxDynamicSharedMemorySize, SMEM_DYN);

    float* g_Anum_p; cudaGetSymbolAddress((void**)&g_Anum_p, g_Anum);
    float* g_W1p_p;  cudaGetSymbolAddress((void**)&g_W1p_p,  g_W1p);
    float* g_W2p_p;  cudaGetSymbolAddress((void**)&g_W2p_p,  g_W2p);
    float* g_Wfp_p;  cudaGetSymbolAddress((void**)&g_Wfp_p,  g_Wfp);

    prep_anum<<<32, 256>>>(w_num, W_first);
    prep_c1<<<32, 256>>>(b_num, W_first);
    prep_c2<<<1, 256>>>(b_first);
    pack_w<<<2048, 256>>>(W1s, g_W1p_p, 8 * 256, 512);
    pack_w<<<2048, 256>>>(W2s, g_W2p_p, 8 * 512, 256);
    pack_w<<<64,   256>>>(g_Anum_p, g_Wfp_p, 32, 256);
    pack_w<<<2048, 256>>>(W_first + (size_t)8192 * 256, g_Wfp_p + 8192, 4096, 256);

    fused_net<<<256, 256, SMEM_DYN>>>(
        x_num, xidx, cat_emb, b1s, b2s, ln_g, ln_b,
        g_f, beta_f, W_head, b_head, (float*)d_out);
}

// round 9
// speedup vs baseline: 1.0736x; 1.0017x over previous
#include <cuda_runtime.h>
#include <cstdint>

// ---------------- problem constants ----------------
static constexpr int Bsz = 16384;
static constexpr int SMEM_DYN = 104 * 1024 + 1024;   // ln 64K + tchunk 8K + wbuf 32K (+align)

// ---------------- device scratch ----------------
__device__ float g_Anum[32 * 256];
__device__ float g_c[256];
__device__ float g_cpart[32 * 256];
__device__ float g_W1p[8 * 8  * 512 * 32];   // [l][kb][n(512)][32] swizzled tf32
__device__ float g_W2p[8 * 16 * 256 * 32];   // [l][kb][n(256)][32] swizzled tf32
__device__ float g_Wfp[129 * 256 * 32];      // first-layer packed (kb0 = folded numeric)

// ---------------- PTX helpers ----------------
__device__ __forceinline__ uint32_t sm32(const void* p) {
    uint32_t a;
    asm("{ .reg .u64 t; cvta.to.shared.u64 t, %1; cvt.u32.u64 %0, t; }" : "=r"(a) : "l"(p));
    return a;
}
__device__ __forceinline__ void cpa16(uint32_t dst, const void* src) {
    asm volatile("cp.async.cg.shared.global [%0], [%1], 16;" :: "r"(dst), "l"(src));
}
#define CPA_COMMIT() asm volatile("cp.async.commit_group;" ::: "memory")
#define CPA_WAIT(n)  asm volatile("cp.async.wait_group %0;" :: "n"(n) : "memory")

__device__ __forceinline__ void ldm4(uint32_t (&r)[4], uint32_t addr) {
    asm volatile("ldmatrix.sync.aligned.m8n8.x4.shared.b16 {%0,%1,%2,%3}, [%4];"
                 : "=r"(r[0]), "=r"(r[1]), "=r"(r[2]), "=r"(r[3]) : "r"(addr));
}
__device__ __forceinline__ uint32_t to_tf32(uint32_t v) {
    uint32_t o;
    asm("cvt.rna.tf32.f32 %0, %1;" : "=r"(o) : "f"(__uint_as_float(v)));
    return o;
}
__device__ __forceinline__ float round_tf32(float v) {
    uint32_t o;
    asm("cvt.rna.tf32.f32 %0, %1;" : "=r"(o) : "f"(v));
    return __uint_as_float(o);
}
__device__ __forceinline__ void mma_tf32(float (&d)[4], const uint32_t (&a)[4],
                                         uint32_t b0, uint32_t b1) {
    asm volatile("mma.sync.aligned.m16n8k8.row.col.f32.tf32.tf32.f32 "
                 "{%0,%1,%2,%3}, {%4,%5,%6,%7}, {%8,%9}, {%0,%1,%2,%3};"
                 : "+f"(d[0]), "+f"(d[1]), "+f"(d[2]), "+f"(d[3])
                 : "r"(a[0]), "r"(a[1]), "r"(a[2]), "r"(a[3]), "r"(b0), "r"(b1));
}
__device__ __forceinline__ void st2s(uint32_t addr, float x, float y) {
    asm volatile("st.shared.v2.f32 [%0], {%1, %2};" :: "r"(addr), "f"(x), "f"(y));
}

// ---------------- prep kernels (5 launches total before fused_net) --------
__global__ void prep_anum(const float* __restrict__ w_num, const float* __restrict__ W_first) {
    int f = blockIdx.x, j = threadIdx.x;
    const float* Wf = W_first + (size_t)f * 256 * 256 + j;
    const float* wn = w_num + f * 256;
    float acc = 0.f;
    for (int d = 0; d < 256; d++) acc = fmaf(wn[d], Wf[(size_t)d * 256], acc);
    g_Anum[f * 256 + j] = acc;
}
__global__ void prep_c1(const float* __restrict__ b_num, const float* __restrict__ W_first) {
    int b = blockIdx.x, j = threadIdx.x;
    float acc = 0.f;
    const float* W = W_first + (size_t)b * 256 * 256 + j;
    const float* bn = b_num + b * 256;
    for (int k = 0; k < 256; k++) acc = fmaf(bn[k], W[(size_t)k * 256], acc);
    g_cpart[b * 256 + j] = acc;
}
__global__ void prep_c2(const float* __restrict__ b_first) {
    int j = threadIdx.x;
    float acc = b_first[j];
    for (int b = 0; b < 32; b++) acc += g_cpart[b * 256 + j];
    g_c[j] = acc;
}

// Coalesced pack of one (kb, 256-col segment): src row-major (Ktot x N) ->
// dst [kb][n][32] swizzled + tf32-rounded. smem transpose, conflict-free.
__device__ __forceinline__ void pack_tile(const float* __restrict__ src,
                                          float* __restrict__ dst,
                                          int kb, int n0, int N) {
    __shared__ float ts[32][257];
    int tid = threadIdx.x;
    for (int r = 0; r < 32; r++)
        ts[r][tid] = src[(size_t)(kb * 32 + r) * N + n0 + tid];
    __syncthreads();
    int j = tid & 31;
    for (int nn = tid >> 5; nn < 256; nn += 8) {
        int n = n0 + nn;
        int k = (((j >> 2) ^ (n & 7)) << 2) | (j & 3);
        dst[((size_t)kb * N + n) * 32 + j] = round_tf32(ts[k][nn]);
    }
}
// W1s (8*256 x 512) + W2s (8*512 x 256)
__global__ void pack_A(const float* __restrict__ W1s, const float* __restrict__ W2s) {
    int b = blockIdx.x;
    if (b < 128) pack_tile(W1s, g_W1p, b >> 1, (b & 1) * 256, 512);
    else         pack_tile(W2s, g_W2p, b - 128, 0, 256);
}
// g_Anum (32 x 256) -> Wfp kb0;  W_first cat rows (4096 x 256) -> Wfp kb1..128
__global__ void pack_B(const float* __restrict__ Wcat) {
    int b = blockIdx.x;
    if (b == 0) pack_tile(g_Anum, g_Wfp, 0, 0, 256);
    else        pack_tile(Wcat, g_Wfp + 8192, b - 1, 0, 256);
}

// =====================================================================
// Persistent fused network kernel. One CTA = 64 rows, 256 threads, occ 2.
// Weight loads split into 16KB halves (B0/B1); each load overlaps one
// compute stage. Residual stream h lives in registers.
// =====================================================================
__global__ __launch_bounds__(256, 2) void fused_net(
    const float* __restrict__ xnum, const int* __restrict__ xidx,
    const float* __restrict__ cemb,
    const float* __restrict__ b1g, const float* __restrict__ b2g,
    const float* __restrict__ lng, const float* __restrict__ lnbet,
    const float* __restrict__ gf,  const float* __restrict__ betf,
    const float* __restrict__ Wh,  const float* __restrict__ bh,
    float* __restrict__ out)
{
    extern __shared__ float dsm[];
    __shared__ float red_s[64 * 4], red_q[64 * 4];
    __shared__ int s_xidx[64 * 16];
    uint32_t raw  = sm32(dsm);
    uint32_t base = (raw + 1023u) & ~1023u;
    const uint32_t LNB = base;            // 64 KB: ln tile, 8 chunks of (64r x 32k)
    const uint32_t TCH = base + 65536u;   //  8 KB: t chunk (64r x 32k)
    const uint32_t B0  = base + 73728u;   // 16 KB weight half-buffer
    const uint32_t B1  = base + 90112u;   // 16 KB weight half-buffer

    int tid = threadIdx.x, wid = tid >> 5, lane = tid & 31;
    int bm = blockIdx.x * 64;
    int warp_m = wid & 1, warp_n = wid >> 1;   // GEMM2 / phase0: 2 x 4 (64 x 256)
    int wm1 = wid & 3,    wn1 = wid >> 2;      // GEMM1: 4 x 2 (64 x 32)
    int lr = lane & 7, lh = (lane >> 3) & 1, lg = lane >> 4;

    float hreg[16][4];
#pragma unroll
    for (int t = 0; t < 16; t++)
#pragma unroll
        for (int q = 0; q < 4; q++) hreg[t][q] = 0.f;

    // cache categorical indices for this CTA's 64 rows
    for (int i = tid; i < 64 * 16; i += 256) s_xidx[i] = xidx[bm * 16 + i];
    __syncthreads();

    // ================= Phase 0: first GEMM (gathered A, K=4128) ==========
    {
        int ar = tid >> 2, aq = tid & 3;
        auto issue = [&](int c, int b) {
            const float* arow;
            if (c == 0) arow = xnum + (size_t)(bm + ar) * 32;
            else {
                int cc = c - 1, f = cc >> 3, d0 = (cc & 7) << 5;
                arow = cemb + (size_t)s_xidx[ar * 16 + f] * 256 + d0;
            }
            uint32_t Ad = base + (uint32_t)b * 8192u + (uint32_t)ar * 128u;
#pragma unroll
            for (int i = 0; i < 2; i++) {
                int g = aq + i * 4;
                cpa16(Ad + (uint32_t)((g ^ (ar & 7)) << 4), arow + g * 4);
            }
            const float4* bsrc = (const float4*)(g_Wfp + (size_t)c * 8192) + tid;
            uint32_t Bd = base + 16384u + (uint32_t)b * 32768u + (uint32_t)tid * 16u;
#pragma unroll
            for (int i = 0; i < 8; i++) cpa16(Bd + (uint32_t)i * 4096u, bsrc + i * 256);
            CPA_COMMIT();
        };
        issue(0, 0);
        issue(1, 1);
#pragma unroll 1
        for (int c = 0; c < 129; c++) {
            if (c + 1 < 129) CPA_WAIT(1); else CPA_WAIT(0);
            __syncthreads();
            uint32_t Ab = base + (uint32_t)(c & 1) * 8192u;
            uint32_t Bb = base + 16384u + (uint32_t)(c & 1) * 32768u;
#pragma unroll
            for (int s = 0; s < 4; s++) {
                uint32_t af[2][4];
#pragma unroll
                for (int i = 0; i < 2; i++) {
                    int R = warp_m * 32 + i * 16 + lr + lh * 8;
                    int g = s * 2 + lg;
                    ldm4(af[i], Ab + (uint32_t)(R * 128 + ((g ^ (R & 7)) << 4)));
#pragma unroll
                    for (int q = 0; q < 4; q++) af[i][q] = to_tf32(af[i][q]);
                }
                uint32_t bf[8][2];
#pragma unroll
                for (int p = 0; p < 4; p++) {
                    int n = warp_n * 64 + p * 16 + lr + lh * 8;
                    int g = s * 2 + lg;
                    uint32_t t4[4];
                    ldm4(t4, Bb + (uint32_t)(n * 128 + ((g ^ (n & 7)) << 4)));
                    bf[2 * p][0] = t4[0]; bf[2 * p + 1][0] = t4[1];
                    bf[2 * p][1] = t4[2]; bf[2 * p + 1][1] = t4[3];
                }
#pragma unroll
                for (int i = 0; i < 2; i++)
#pragma unroll
                    for (int j = 0; j < 8; j++)
                        mma_tf32(hreg[i * 8 + j], af[i], bf[j][0], bf[j][1]);
            }
            __syncthreads();
            if (c + 2 < 129) issue(c + 2, c & 1);
        }
        // folded bias
#pragma unroll
        for (int i = 0; i < 2; i++)
#pragma unroll
            for (int j = 0; j < 8; j++) {
                int col = warp_n * 64 + j * 8 + (lane & 3) * 2;
                float b0 = g_c[col], b1 = g_c[col + 1];
                hreg[i * 8 + j][0] += b0; hreg[i * 8 + j][1] += b1;
                hreg[i * 8 + j][2] += b0; hreg[i * 8 + j][3] += b1;
            }
    }

    // ---- half-size weight loaders (16KB each, one commit group per call) ----
    auto issueW1h = [&](const float* W1, int kc, int half, uint32_t B) {
#pragma unroll
        for (int i = 0; i < 4; i++) {
            int kb = half * 4 + i;
            cpa16(B + (uint32_t)(i * 4096 + tid * 16),
                  W1 + ((size_t)kb * 512 + kc * 32) * 32 + tid * 4);
        }
        CPA_COMMIT();
    };
    auto issueW2h = [&](const float* W2, int kc, int half, uint32_t B) {
        const float* src = W2 + (size_t)kc * 8192;
#pragma unroll
        for (int i = 0; i < 4; i++) {
            int pg = 2 * i + half;
            cpa16(B + (uint32_t)(i * 4096 + tid * 16), src + pg * 1024 + tid * 4);
        }
        CPA_COMMIT();
    };

    // ---- LN from hreg -> ln smem (tf32-rounded) ----
    auto do_ln = [&](const float* gam, const float* bet) {
        float rs_[4] = {0.f, 0.f, 0.f, 0.f}, rq_[4] = {0.f, 0.f, 0.f, 0.f};
#pragma unroll
        for (int i = 0; i < 2; i++)
#pragma unroll
            for (int j = 0; j < 8; j++) {
                float v0 = hreg[i * 8 + j][0], v1 = hreg[i * 8 + j][1];
                float v2 = hreg[i * 8 + j][2], v3 = hreg[i * 8 + j][3];
                rs_[i * 2 + 0] += v0 + v1;  rq_[i * 2 + 0] += v0 * v0 + v1 * v1;
                rs_[i * 2 + 1] += v2 + v3;  rq_[i * 2 + 1] += v2 * v2 + v3 * v3;
            }
#pragma unroll
        for (int t = 0; t < 4; t++)
#pragma unroll
            for (int o = 1; o <= 2; o <<= 1) {
                rs_[t] += __shfl_xor_sync(0xffffffffu, rs_[t], o);
                rq_[t] += __shfl_xor_sync(0xffffffffu, rq_[t], o);
            }
        if ((lane & 3) == 0) {
#pragma unroll
            for (int i = 0; i < 2; i++)
#pragma unroll
                for (int h = 0; h < 2; h++) {
                    int rloc = warp_m * 32 + i * 16 + h * 8 + (lane >> 2);
                    red_s[rloc * 4 + warp_n] = rs_[i * 2 + h];
                    red_q[rloc * 4 + warp_n] = rq_[i * 2 + h];
                }
        }
        __syncthreads();
#pragma unroll
        for (int i = 0; i < 2; i++)
#pragma unroll
            for (int h = 0; h < 2; h++) {
                int rloc = warp_m * 32 + i * 16 + h * 8 + (lane >> 2);
                float s = red_s[rloc * 4 + 0] + red_s[rloc * 4 + 1]
                        + red_s[rloc * 4 + 2] + red_s[rloc * 4 + 3];
                float q = red_q[rloc * 4 + 0] + red_q[rloc * 4 + 1]
                        + red_q[rloc * 4 + 2] + red_q[rloc * 4 + 3];
                float mu = s * (1.f / 256.f);
                float rinv = rsqrtf(q * (1.f / 256.f) - mu * mu + 1e-5f);
#pragma unroll
                for (int j = 0; j < 8; j++) {
                    int col = warp_n * 64 + j * 8 + (lane & 3) * 2;
                    float y0 = round_tf32((hreg[i * 8 + j][h * 2 + 0] - mu) * rinv * gam[col]     + bet[col]);
                    float y1 = round_tf32((hreg[i * 8 + j][h * 2 + 1] - mu) * rinv * gam[col + 1] + bet[col + 1]);
                    int cc = col & 31, kb = col >> 5;
                    uint32_t addr = LNB + (uint32_t)(kb * 8192 + rloc * 128
                                   + (((cc >> 2) ^ (rloc & 7)) << 4) + (cc & 3) * 4);
                    st2s(addr, y0, y1);
                }
            }
        __syncthreads();
    };

    // GEMM2 half: warp's piece lives at B + warp_n*4096
    auto g2half = [&](uint32_t B, int half) {
#pragma unroll
        for (int s = 0; s < 4; s++) {
            int g = s * 2 + lg;
            uint32_t af[2][4];
#pragma unroll
            for (int i = 0; i < 2; i++) {
                int R = warp_m * 32 + i * 16 + lr + lh * 8;
                ldm4(af[i], TCH + (uint32_t)(R * 128 + ((g ^ (R & 7)) << 4)));
            }
            uint32_t bf[4][2];
#pragma unroll
            for (int pp = 0; pp < 2; pp++) {
                int nloc = pp * 16 + lr + lh * 8;
                uint32_t t4[4];
                ldm4(t4, B + (uint32_t)(warp_n * 4096 + nloc * 128 + ((g ^ (nloc & 7)) << 4)));
                bf[2 * pp][0] = t4[0]; bf[2 * pp + 1][0] = t4[1];
                bf[2 * pp][1] = t4[2]; bf[2 * pp + 1][1] = t4[3];
            }
#pragma unroll
            for (int i = 0; i < 2; i++)
#pragma unroll
                for (int jj = 0; jj < 4; jj++)
                    mma_tf32(hreg[i * 8 + half * 4 + jj], af[i], bf[jj][0], bf[jj][1]);
        }
    };

    // prologue: W1 half0 of layer 0, kc 0 -> B0
    issueW1h(g_W1p, 0, 0, B0);

    // ================= 8 residual layers =================
#pragma unroll 1
    for (int l = 0; l < 8; l++) {
        do_ln(lng + l * 256, lnbet + l * 256);
        const float* W1 = g_W1p + (size_t)l * 8 * 512 * 32;
        const float* W2 = g_W2p + (size_t)l * 16 * 256 * 32;
        const float* b1 = b1g + l * 512;
#pragma unroll 1
        for (int kc = 0; kc < 16; kc++) {
            float a1[2][4] = {};
            // ---- S1: wait W1a; issue W1b; GEMM1 kb0-3 ----
            CPA_WAIT(0);
            __syncthreads();
            issueW1h(W1, kc, 1, B1);
#pragma unroll
            for (int kb = 0; kb < 4; kb++) {
#pragma unroll
                for (int s = 0; s < 4; s++) {
                    int g = s * 2 + lg;
                    uint32_t af[4];
                    int R = wm1 * 16 + lr + lh * 8;
                    ldm4(af, LNB + (uint32_t)(kb * 8192 + R * 128 + ((g ^ (R & 7)) << 4)));
                    int n = wn1 * 16 + lr + lh * 8;
                    uint32_t t4[4];
                    ldm4(t4, B0 + (uint32_t)(kb * 4096 + n * 128 + ((g ^ (n & 7)) << 4)));
                    mma_tf32(a1[0], af, t4[0], t4[2]);
                    mma_tf32(a1[1], af, t4[1], t4[3]);
                }
            }
            // ---- S2: wait W1b; issue W2even; GEMM1 kb4-7; TCH ----
            CPA_WAIT(0);
            __syncthreads();
            issueW2h(W2, kc, 0, B0);
#pragma unroll
            for (int kb = 4; kb < 8; kb++) {
#pragma unroll
                for (int s = 0; s < 4; s++) {
                    int g = s * 2 + lg;
                    uint32_t af[4];
                    int R = wm1 * 16 + lr + lh * 8;
                    ldm4(af, LNB + (uint32_t)(kb * 8192 + R * 128 + ((g ^ (R & 7)) << 4)));
                    int n = wn1 * 16 + lr + lh * 8;
                    uint32_t t4[4];
                    ldm4(t4, B1 + (uint32_t)((kb - 4) * 4096 + n * 128 + ((g ^ (n & 7)) << 4)));
                    mma_tf32(a1[0], af, t4[0], t4[2]);
                    mma_tf32(a1[1], af, t4[1], t4[3]);
                }
            }
#pragma unroll
            for (int f = 0; f < 2; f++) {
                int row0 = wm1 * 16 + (lane >> 2);
                int colL = wn1 * 16 + f * 8 + (lane & 3) * 2;
                int gc = kc * 32 + colL;
                float bb0 = b1[gc], bb1 = b1[gc + 1];
                float t0 = round_tf32(fmaxf(a1[f][0] + bb0, 0.f));
                float t1 = round_tf32(fmaxf(a1[f][1] + bb1, 0.f));
                float t2 = round_tf32(fmaxf(a1[f][2] + bb0, 0.f));
                float t3 = round_tf32(fmaxf(a1[f][3] + bb1, 0.f));
                uint32_t sw = (uint32_t)((((colL >> 2) ^ (row0 & 7)) << 4) + (colL & 3) * 4);
                st2s(TCH + (uint32_t)(row0 * 128) + sw, t0, t1);
                st2s(TCH + (uint32_t)((row0 + 8) * 128) + sw, t2, t3);
            }
            // ---- S3: wait W2even; issue W2odd; GEMM2 even ----
            CPA_WAIT(0);
            __syncthreads();
            issueW2h(W2, kc, 1, B1);
            g2half(B0, 0);
            // ---- S4: wait W2odd; issue next W1a; GEMM2 odd ----
            CPA_WAIT(0);
            __syncthreads();
            if (kc < 15)    issueW1h(W1, kc + 1, 0, B0);
            else if (l < 7) issueW1h(g_W1p + (size_t)(l + 1) * 8 * 512 * 32, 0, 0, B0);
            g2half(B1, 1);
        }
        const float* b2 = b2g + l * 256;
#pragma unroll
        for (int i = 0; i < 2; i++)
#pragma unroll
            for (int j = 0; j < 8; j++) {
                int col = warp_n * 64 + j * 8 + (lane & 3) * 2;
                float b0 = b2[col], b1v = b2[col + 1];
                hreg[i * 8 + j][0] += b0;  hreg[i * 8 + j][1] += b1v;
                hreg[i * 8 + j][2] += b0;  hreg[i * 8 + j][3] += b1v;
            }
    }

    // ================= final LN + head =================
    {
        float rs_[4] = {0.f, 0.f, 0.f, 0.f}, rq_[4] = {0.f, 0.f, 0.f, 0.f};
#pragma unroll
        for (int i = 0; i < 2; i++)
#pragma unroll
            for (int j = 0; j < 8; j++) {
                float v0 = hreg[i * 8 + j][0], v1 = hreg[i * 8 + j][1];
                float v2 = hreg[i * 8 + j][2], v3 = hreg[i * 8 + j][3];
                rs_[i * 2 + 0] += v0 + v1;  rq_[i * 2 + 0] += v0 * v0 + v1 * v1;
                rs_[i * 2 + 1] += v2 + v3;  rq_[i * 2 + 1] += v2 * v2 + v3 * v3;
            }
#pragma unroll
        for (int t = 0; t < 4; t++)
#pragma unroll
            for (int o = 1; o <= 2; o <<= 1) {
                rs_[t] += __shfl_xor_sync(0xffffffffu, rs_[t], o);
                rq_[t] += __shfl_xor_sync(0xffffffffu, rq_[t], o);
            }
        if ((lane & 3) == 0) {
#pragma unroll
            for (int i = 0; i < 2; i++)
#pragma unroll
                for (int h = 0; h < 2; h++) {
                    int rloc = warp_m * 32 + i * 16 + h * 8 + (lane >> 2);
                    red_s[rloc * 4 + warp_n] = rs_[i * 2 + h];
                    red_q[rloc * 4 + warp_n] = rq_[i * 2 + h];
                }
        }
        __syncthreads();
        float hd0[4] = {0.f, 0.f, 0.f, 0.f}, hd1[4] = {0.f, 0.f, 0.f, 0.f};
#pragma unroll
        for (int i = 0; i < 2; i++)
#pragma unroll
            for (int h = 0; h < 2; h++) {
                int rloc = warp_m * 32 + i * 16 + h * 8 + (lane >> 2);
                float s = red_s[rloc * 4 + 0] + red_s[rloc * 4 + 1]
                        + red_s[rloc * 4 + 2] + red_s[rloc * 4 + 3];
                float q = red_q[rloc * 4 + 0] + red_q[rloc * 4 + 1]
                        + red_q[rloc * 4 + 2] + red_q[rloc * 4 + 3];
                float mu = s * (1.f / 256.f);
                float rinv = rsqrtf(q * (1.f / 256.f) - mu * mu + 1e-5f);
#pragma unroll
                for (int j = 0; j < 8; j++) {
                    int col = warp_n * 64 + j * 8 + (lane & 3) * 2;
                    float y0 = (hreg[i * 8 + j][h * 2 + 0] - mu) * rinv * gf[col]     + betf[col];
                    float y1 = (hreg[i * 8 + j][h * 2 + 1] - mu) * rinv * gf[col + 1] + betf[col + 1];
                    hd0[i * 2 + h] += y0 * Wh[col * 2 + 0] + y1 * Wh[col * 2 + 2];
                    hd1[i * 2 + h] += y0 * Wh[col * 2 + 1] + y1 * Wh[col * 2 + 3];
                }
            }
#pragma unroll
        for (int t = 0; t < 4; t++)
#pragma unroll
            for (int o = 1; o <= 2; o <<= 1) {
                hd0[t] += __shfl_xor_sync(0xffffffffu, hd0[t], o);
                hd1[t] += __shfl_xor_sync(0xffffffffu, hd1[t], o);
            }
        __syncthreads();
        if ((lane & 3) == 0) {
#pragma unroll
            for (int i = 0; i < 2; i++)
#pragma unroll
                for (int h = 0; h < 2; h++) {
                    int rloc = warp_m * 32 + i * 16 + h * 8 + (lane >> 2);
                    red_s[rloc * 4 + warp_n] = hd0[i * 2 + h];
                    red_q[rloc * 4 + warp_n] = hd1[i * 2 + h];
                }
        }
        __syncthreads();
        if (tid < 64) {
            float s0 = red_s[tid * 4 + 0] + red_s[tid * 4 + 1]
                     + red_s[tid * 4 + 2] + red_s[tid * 4 + 3];
            float s1 = red_q[tid * 4 + 0] + red_q[tid * 4 + 1]
                     + red_q[tid * 4 + 2] + red_q[tid * 4 + 3];
            out[(bm + tid) * 2 + 0] = s0 + bh[0];
            out[(bm + tid) * 2 + 1] = s1 + bh[1];
        }
    }
}

// ---------------- launch (exactly 6 kernels; fused_net is #6 for ncu -s 5) ----
extern "C" void kernel_launch(void* const* d_in, const int* in_sizes, int n_in,
                              void* d_out, int out_size) {
    const float* x_num   = (const float*)d_in[0];
    const int*   xidx    = (const int*)  d_in[1];
    const float* w_num   = (const float*)d_in[2];
    const float* b_num   = (const float*)d_in[3];
    const float* cat_emb = (const float*)d_in[4];
    const float* W_first = (const float*)d_in[5];
    const float* b_first = (const float*)d_in[6];
    const float* ln_g    = (const float*)d_in[7];
    const float* ln_b    = (const float*)d_in[8];
    const float* W1s     = (const float*)d_in[9];
    const float* b1s     = (const float*)d_in[10];
    const float* W2s     = (const float*)d_in[11];
    const float* b2s     = (const float*)d_in[12];
    const float* g_f     = (const float*)d_in[13];
    const float* beta_f  = (const float*)d_in[14];
    const float* W_head  = (const float*)d_in[15];
    const float* b_head  = (const float*)d_in[16];

    cudaFuncSetAttribute(fused_net, cudaFuncAttributeMaxDynamicSharedMemorySize, SMEM_DYN);

    prep_anum<<<32, 256>>>(w_num, W_first);                       // 1
    prep_c1<<<32, 256>>>(b_num, W_first);                         // 2
    prep_c2<<<1, 256>>>(b_first);                                 // 3
    pack_A<<<256, 256>>>(W1s, W2s);                               // 4
    pack_B<<<129, 256>>>(W_first + (size_t)8192 * 256);           // 5

    fused_net<<<256, 256, SMEM_DYN>>>(                            // 6 (profiled)
        x_num, xidx, cat_emb, b1s, b2s, ln_g, ln_b,
        g_f, beta_f, W_head, b_head, (float*)d_out);
}

// round 10
// speedup vs baseline: 1.9358x; 1.8031x over previous
#include <cuda_runtime.h>
#include <cuda_fp16.h>
#include <cstdint>

// ---------------- problem constants ----------------
static constexpr int Bsz = 16384;
static constexpr int SMEM_DYN = 80 * 1024 + 1024;  // max(phase0 80K, layers 72K)

// ---------------- device scratch ----------------
__device__ float  g_Anum[32 * 256];
__device__ float  g_c[256];
__device__ float  g_cpart[32 * 256];
__device__ __half g_W1ph[8 * 8 * 4 * 64 * 64];    // [l][kc][kb][n64][k64] swizzled fp16
__device__ __half g_W2ph[8 * 8 * 8 * 32 * 64];    // [l][kc][piece][n32][k64]
__device__ __half g_Wfph[65 * 256 * 64];          // [chunk][n256][k64] (chunk0 = numeric+zeros)

// ---------------- PTX helpers ----------------
__device__ __forceinline__ uint32_t sm32(const void* p) {
    uint32_t a;
    asm("{ .reg .u64 t; cvta.to.shared.u64 t, %1; cvt.u32.u64 %0, t; }" : "=r"(a) : "l"(p));
    return a;
}
__device__ __forceinline__ void cpa16(uint32_t dst, const void* src) {
    asm volatile("cp.async.cg.shared.global [%0], [%1], 16;" :: "r"(dst), "l"(src));
}
#define CPA_COMMIT() asm volatile("cp.async.commit_group;" ::: "memory")
#define CPA_WAIT(n)  asm volatile("cp.async.wait_group %0;" :: "n"(n) : "memory")

__device__ __forceinline__ void ldm4(uint32_t (&r)[4], uint32_t addr) {
    asm volatile("ldmatrix.sync.aligned.m8n8.x4.shared.b16 {%0,%1,%2,%3}, [%4];"
                 : "=r"(r[0]), "=r"(r[1]), "=r"(r[2]), "=r"(r[3]) : "r"(addr));
}
__device__ __forceinline__ void mma_f16(float (&d)[4], const uint32_t (&a)[4],
                                        uint32_t b0, uint32_t b1) {
    asm volatile("mma.sync.aligned.m16n8k16.row.col.f32.f16.f16.f32 "
                 "{%0,%1,%2,%3}, {%4,%5,%6,%7}, {%8,%9}, {%0,%1,%2,%3};"
                 : "+f"(d[0]), "+f"(d[1]), "+f"(d[2]), "+f"(d[3])
                 : "r"(a[0]), "r"(a[1]), "r"(a[2]), "r"(a[3]), "r"(b0), "r"(b1));
}
__device__ __forceinline__ uint32_t f2h2(float lo, float hi) {
    uint32_t r;
    asm("cvt.rn.f16x2.f32 %0, %1, %2;" : "=r"(r) : "f"(hi), "f"(lo));
    return r;
}
__device__ __forceinline__ void st1s(uint32_t a, uint32_t v) {
    asm volatile("st.shared.b32 [%0], %1;" :: "r"(a), "r"(v));
}
__device__ __forceinline__ void st4s(uint32_t a, uint32_t x, uint32_t y, uint32_t z, uint32_t w) {
    asm volatile("st.shared.v4.b32 [%0], {%1,%2,%3,%4};" :: "r"(a), "r"(x), "r"(y), "r"(z), "r"(w));
}

// ---------------- prep kernels ----------------
__global__ void prep_anum(const float* __restrict__ w_num, const float* __restrict__ W_first) {
    int f = blockIdx.x, j = threadIdx.x;
    const float* Wf = W_first + (size_t)f * 256 * 256 + j;
    const float* wn = w_num + f * 256;
    float acc = 0.f;
    for (int d = 0; d < 256; d++) acc = fmaf(wn[d], Wf[(size_t)d * 256], acc);
    g_Anum[f * 256 + j] = acc;
}
__global__ void prep_c1(const float* __restrict__ b_num, const float* __restrict__ W_first) {
    int b = blockIdx.x, j = threadIdx.x;
    float acc = 0.f;
    const float* W = W_first + (size_t)b * 256 * 256 + j;
    const float* bn = b_num + b * 256;
    for (int k = 0; k < 256; k++) acc = fmaf(bn[k], W[(size_t)k * 256], acc);
    g_cpart[b * 256 + j] = acc;
}
__global__ void prep_c2(const float* __restrict__ b_first) {
    int j = threadIdx.x;
    float acc = b_first[j];
    for (int b = 0; b < 32; b++) acc += g_cpart[b * 256 + j];
    g_c[j] = acc;
}
// swizzled k for stored slot j (j even), within 64-k row of 8-fp16 groups
__device__ __forceinline__ int swzk(int j, int n) {
    return (((j >> 3) ^ (n & 7)) << 3) | (j & 7);
}
__global__ void pack_w1(const float* __restrict__ W1s) {
    for (int i = blockIdx.x * blockDim.x + threadIdx.x; i < 524288; i += gridDim.x * blockDim.x) {
        int j = (i & 31) * 2, n = (i >> 5) & 63, kb = (i >> 11) & 3, kc = (i >> 13) & 7, l = i >> 16;
        int k = swzk(j, n);
        const float* s = W1s + (size_t)(l * 256 + kb * 64 + k) * 512 + kc * 64 + n;
        ((__half2*)g_W1ph)[i] = __floats2half2_rn(s[0], s[512]);
    }
}
__global__ void pack_w2(const float* __restrict__ W2s) {
    for (int i = blockIdx.x * blockDim.x + threadIdx.x; i < 524288; i += gridDim.x * blockDim.x) {
        int j = (i & 31) * 2, n = (i >> 5) & 31, p = (i >> 10) & 7, kc = (i >> 13) & 7, l = i >> 16;
        int k = swzk(j, n);
        const float* s = W2s + (size_t)(l * 512 + kc * 64 + k) * 256 + p * 32 + n;
        ((__half2*)g_W2ph)[i] = __floats2half2_rn(s[0], s[256]);
    }
}
__global__ void pack_wf(const float* __restrict__ Wcat) {
    for (int i = blockIdx.x * blockDim.x + threadIdx.x; i < 65 * 256 * 32; i += gridDim.x * blockDim.x) {
        int j = (i & 31) * 2, n = (i >> 5) & 255, c = i >> 13;
        int k = swzk(j, n);
        float v0, v1;
        if (c == 0) {
            v0 = (k < 32) ? g_Anum[k * 256 + n] : 0.f;
            v1 = (k < 32) ? g_Anum[(k + 1) * 256 + n] : 0.f;
        } else {
            const float* s = Wcat + (size_t)((c - 1) * 64 + k) * 256 + n;
            v0 = s[0]; v1 = s[256];
        }
        ((__half2*)g_Wfph)[i] = __floats2half2_rn(v0, v1);
    }
}

// =====================================================================
// Persistent fused network kernel (fp16 operands, fp32 accum).
// One CTA = 64 rows, 256 threads, occ 2. h-residual lives in fp32 regs.
// =====================================================================
__global__ __launch_bounds__(256, 2) void fused_net(
    const float* __restrict__ xnum, const int* __restrict__ xidx,
    const float* __restrict__ cemb,
    const float* __restrict__ b1g, const float* __restrict__ b2g,
    const float* __restrict__ lng, const float* __restrict__ lnbet,
    const float* __restrict__ gf,  const float* __restrict__ betf,
    const float* __restrict__ Wh,  const float* __restrict__ bh,
    float* __restrict__ out)
{
    extern __shared__ float dsm[];
    __shared__ float red_s[64 * 4], red_q[64 * 4];
    __shared__ int s_xidx[64 * 16];
    uint32_t raw  = sm32(dsm);
    uint32_t base = (raw + 1023u) & ~1023u;
    // layers: LNB 32K | TCH 8K | B0 16K | B1 16K   (72K)
    const uint32_t LNB = base;
    const uint32_t TCH = base + 32768u;
    const uint32_t B0  = base + 40960u;
    const uint32_t B1  = base + 57344u;
    // phase 0: A0 8K | A1 8K | Bb0 32K | Bb1 32K   (80K)
    const uint32_t P0A = base;
    const uint32_t P0B = base + 16384u;

    int tid = threadIdx.x, wid = tid >> 5, lane = tid & 31;
    int bm = blockIdx.x * 64;
    int warp_m = wid & 1, warp_n = wid >> 1;   // phase0/GEMM2: 2m x 4n (64 x 256)
    int wm1 = wid & 3,    wn1 = wid >> 2;      // GEMM1: 4m x 2n (64 x 64)
    int lr = lane & 7, lh = (lane >> 3) & 1, lg = lane >> 4;

    float hreg[16][4];
#pragma unroll
    for (int t = 0; t < 16; t++)
#pragma unroll
        for (int q = 0; q < 4; q++) hreg[t][q] = 0.f;

    for (int i = tid; i < 64 * 16; i += 256) s_xidx[i] = xidx[bm * 16 + i];
    __syncthreads();

    // ================= Phase 0: first GEMM, 65 chunks of 64 k =================
    {
        int ar = tid >> 2, aq = tid & 3;   // 4 threads per A row; 16 fp32 each
        float4 R4[4];
        auto ldgA = [&](int c) {
            if (c == 0) {
                if (aq < 2) {
                    const float4* s = (const float4*)(xnum + (size_t)(bm + ar) * 32 + aq * 16);
#pragma unroll
                    for (int i = 0; i < 4; i++) R4[i] = s[i];
                } else {
#pragma unroll
                    for (int i = 0; i < 4; i++) R4[i] = make_float4(0.f, 0.f, 0.f, 0.f);
                }
            } else {
                int cc = c - 1, f = cc >> 2, d0 = (cc & 3) << 6;
                const float4* s = (const float4*)(cemb + (size_t)s_xidx[ar * 16 + f] * 256 + d0 + aq * 16);
#pragma unroll
                for (int i = 0; i < 4; i++) R4[i] = s[i];
            }
        };
        auto stsA = [&](int b) {
            uint32_t bufa = P0A + (uint32_t)b * 8192u + (uint32_t)ar * 128u;
#pragma unroll
            for (int t = 0; t < 2; t++) {
                int g = aq * 2 + t;
                uint32_t a = bufa + (uint32_t)((g ^ (ar & 7)) << 4);
                st4s(a, f2h2(R4[2 * t].x, R4[2 * t].y), f2h2(R4[2 * t].z, R4[2 * t].w),
                        f2h2(R4[2 * t + 1].x, R4[2 * t + 1].y), f2h2(R4[2 * t + 1].z, R4[2 * t + 1].w));
            }
        };
        auto cpB = [&](int c, int b) {
            const float4* src = (const float4*)(g_Wfph + (size_t)c * 16384) + tid;
            uint32_t Bd = P0B + (uint32_t)b * 32768u + (uint32_t)tid * 16u;
#pragma unroll
            for (int i = 0; i < 8; i++) cpa16(Bd + (uint32_t)i * 4096u, src + i * 256);
            CPA_COMMIT();
        };

        ldgA(0);
        cpB(0, 0); cpB(1, 1);
#pragma unroll 1
        for (int c = 0; c <= 64; c++) {
            int b = c & 1;
            stsA(b);
            if (c < 64) ldgA(c + 1);
            if (c + 1 <= 64) CPA_WAIT(1); else CPA_WAIT(0);
            __syncthreads();
            uint32_t Ab = P0A + (uint32_t)b * 8192u;
            uint32_t Bb = P0B + (uint32_t)b * 32768u;
#pragma unroll
            for (int s = 0; s < 4; s++) {
                int g = s * 2 + lg;
                uint32_t af[2][4];
#pragma unroll
                for (int i = 0; i < 2; i++) {
                    int R = warp_m * 32 + i * 16 + lr + lh * 8;
                    ldm4(af[i], Ab + (uint32_t)(R * 128 + ((g ^ (R & 7)) << 4)));
                }
                uint32_t bf[8][2];
#pragma unroll
                for (int p = 0; p < 4; p++) {
                    int n = warp_n * 64 + p * 16 + lr + lh * 8;
                    uint32_t t4[4];
                    ldm4(t4, Bb + (uint32_t)(n * 128 + ((g ^ (n & 7)) << 4)));
                    bf[2 * p][0] = t4[0]; bf[2 * p][1] = t4[2];
                    bf[2 * p + 1][0] = t4[1]; bf[2 * p + 1][1] = t4[3];
                }
#pragma unroll
                for (int i = 0; i < 2; i++)
#pragma unroll
                    for (int j = 0; j < 8; j++)
                        mma_f16(hreg[i * 8 + j], af[i], bf[j][0], bf[j][1]);
            }
            __syncthreads();
            if (c + 2 <= 64) cpB(c + 2, b);
        }
        // folded bias
#pragma unroll
        for (int i = 0; i < 2; i++)
#pragma unroll
            for (int j = 0; j < 8; j++) {
                int col = warp_n * 64 + j * 8 + (lane & 3) * 2;
                float b0 = g_c[col], b1 = g_c[col + 1];
                hreg[i * 8 + j][0] += b0; hreg[i * 8 + j][1] += b1;
                hreg[i * 8 + j][2] += b0; hreg[i * 8 + j][3] += b1;
            }
    }

    // ---- weight-half loaders (16 KB each) ----
    auto issueW1h = [&](const __half* W1, int kc, int half, uint32_t B) {
        const float4* src = (const float4*)(W1 + ((size_t)kc * 4 + half * 2) * 4096) + tid;
#pragma unroll
        for (int i = 0; i < 4; i++) cpa16(B + (uint32_t)(tid * 16 + i * 4096), src + i * 256);
        CPA_COMMIT();
    };
    auto issueW2h = [&](const __half* W2, int kc, int half, uint32_t B) {
        const __half* src = W2 + (size_t)kc * 16384;
#pragma unroll
        for (int i = 0; i < 4; i++) {
            int pg = 2 * i + half;
            cpa16(B + (uint32_t)(i * 4096 + tid * 16), src + pg * 2048 + tid * 8);
        }
        CPA_COMMIT();
    };

    // ---- LN from hreg -> LNB (fp16) ----
    auto do_ln = [&](const float* gam, const float* bet) {
        float rs_[4] = {0.f, 0.f, 0.f, 0.f}, rq_[4] = {0.f, 0.f, 0.f, 0.f};
#pragma unroll
        for (int i = 0; i < 2; i++)
#pragma unroll
            for (int j = 0; j < 8; j++) {
                float v0 = hreg[i * 8 + j][0], v1 = hreg[i * 8 + j][1];
                float v2 = hreg[i * 8 + j][2], v3 = hreg[i * 8 + j][3];
                rs_[i * 2 + 0] += v0 + v1;  rq_[i * 2 + 0] += v0 * v0 + v1 * v1;
                rs_[i * 2 + 1] += v2 + v3;  rq_[i * 2 + 1] += v2 * v2 + v3 * v3;
            }
#pragma unroll
        for (int t = 0; t < 4; t++)
#pragma unroll
            for (int o = 1; o <= 2; o <<= 1) {
                rs_[t] += __shfl_xor_sync(0xffffffffu, rs_[t], o);
                rq_[t] += __shfl_xor_sync(0xffffffffu, rq_[t], o);
            }
        if ((lane & 3) == 0) {
#pragma unroll
            for (int i = 0; i < 2; i++)
#pragma unroll
                for (int h = 0; h < 2; h++) {
                    int rloc = warp_m * 32 + i * 16 + h * 8 + (lane >> 2);
                    red_s[rloc * 4 + warp_n] = rs_[i * 2 + h];
                    red_q[rloc * 4 + warp_n] = rq_[i * 2 + h];
                }
        }
        __syncthreads();
#pragma unroll
        for (int i = 0; i < 2; i++)
#pragma unroll
            for (int h = 0; h < 2; h++) {
                int rloc = warp_m * 32 + i * 16 + h * 8 + (lane >> 2);
                float s = red_s[rloc * 4 + 0] + red_s[rloc * 4 + 1]
                        + red_s[rloc * 4 + 2] + red_s[rloc * 4 + 3];
                float q = red_q[rloc * 4 + 0] + red_q[rloc * 4 + 1]
                        + red_q[rloc * 4 + 2] + red_q[rloc * 4 + 3];
                float mu = s * (1.f / 256.f);
                float rinv = rsqrtf(q * (1.f / 256.f) - mu * mu + 1e-5f);
#pragma unroll
                for (int j = 0; j < 8; j++) {
                    int col = warp_n * 64 + j * 8 + (lane & 3) * 2;
                    float y0 = (hreg[i * 8 + j][h * 2 + 0] - mu) * rinv * gam[col]     + bet[col];
                    float y1 = (hreg[i * 8 + j][h * 2 + 1] - mu) * rinv * gam[col + 1] + bet[col + 1];
                    int kcol = col & 63, kb = col >> 6, gg = kcol >> 3;
                    uint32_t addr = LNB + (uint32_t)(kb * 8192 + rloc * 128
                                   + ((gg ^ (rloc & 7)) << 4) + (kcol & 7) * 2);
                    st1s(addr, f2h2(y0, y1));
                }
            }
        __syncthreads();
    };

    // GEMM1 quarter (2 kb-blocks from one 16KB buffer)
    float a1[4][4];
    auto g1quarter = [&](uint32_t B, int kbhalf) {
#pragma unroll
        for (int kb2 = 0; kb2 < 2; kb2++) {
            int kbg = kbhalf * 2 + kb2;
#pragma unroll
            for (int s = 0; s < 4; s++) {
                int g = s * 2 + lg;
                uint32_t af[4];
                int R = wm1 * 16 + lr + lh * 8;
                ldm4(af, LNB + (uint32_t)(kbg * 8192 + R * 128 + ((g ^ (R & 7)) << 4)));
                uint32_t bf[4][2];
#pragma unroll
                for (int pp = 0; pp < 2; pp++) {
                    int n = wn1 * 32 + pp * 16 + lr + lh * 8;
                    uint32_t t4[4];
                    ldm4(t4, B + (uint32_t)(kb2 * 8192 + n * 128 + ((g ^ (n & 7)) << 4)));
                    bf[2 * pp][0] = t4[0]; bf[2 * pp][1] = t4[2];
                    bf[2 * pp + 1][0] = t4[1]; bf[2 * pp + 1][1] = t4[3];
                }
#pragma unroll
                for (int j = 0; j < 4; j++) mma_f16(a1[j], af, bf[j][0], bf[j][1]);
            }
        }
    };
    // GEMM2 half: warp's 32-n piece at B + warp_n*4096
    auto g2half = [&](uint32_t B, int half) {
#pragma unroll
        for (int s = 0; s < 4; s++) {
            int g = s * 2 + lg;
            uint32_t af[2][4];
#pragma unroll
            for (int i = 0; i < 2; i++) {
                int R = warp_m * 32 + i * 16 + lr + lh * 8;
                ldm4(af[i], TCH + (uint32_t)(R * 128 + ((g ^ (R & 7)) << 4)));
            }
            uint32_t bf[4][2];
#pragma unroll
            for (int pp = 0; pp < 2; pp++) {
                int nl = pp * 16 + lr + lh * 8;
                uint32_t t4[4];
                ldm4(t4, B + (uint32_t)(warp_n * 4096 + nl * 128 + ((g ^ (nl & 7)) << 4)));
                bf[2 * pp][0] = t4[0]; bf[2 * pp][1] = t4[2];
                bf[2 * pp + 1][0] = t4[1]; bf[2 * pp + 1][1] = t4[3];
            }
#pragma unroll
            for (int i = 0; i < 2; i++)
#pragma unroll
                for (int jj = 0; jj < 4; jj++)
                    mma_f16(hreg[i * 8 + half * 4 + jj], af[i], bf[jj][0], bf[jj][1]);
        }
    };

    // prologue: W1 half0 of layer 0, kc 0 -> B0
    issueW1h(g_W1ph, 0, 0, B0);

    // ================= 8 residual layers (8 kc of 64 each) =================
#pragma unroll 1
    for (int l = 0; l < 8; l++) {
        do_ln(lng + l * 256, lnbet + l * 256);
        const __half* W1 = g_W1ph + (size_t)l * 8 * 4 * 4096;
        const __half* W2 = g_W2ph + (size_t)l * 8 * 16384;
        const float*  b1 = b1g + l * 512;
#pragma unroll 1
        for (int kc = 0; kc < 8; kc++) {
#pragma unroll
            for (int j = 0; j < 4; j++)
#pragma unroll
                for (int q = 0; q < 4; q++) a1[j][q] = 0.f;
            // S1: wait W1a; issue W1b; GEMM1 kb 0-1
            CPA_WAIT(0);
            __syncthreads();
            issueW1h(W1, kc, 1, B1);
            g1quarter(B0, 0);
            // S2: wait W1b; issue W2even; GEMM1 kb 2-3; relu+bias -> TCH
            CPA_WAIT(0);
            __syncthreads();
            issueW2h(W2, kc, 0, B0);
            g1quarter(B1, 1);
#pragma unroll
            for (int j = 0; j < 4; j++) {
                int row0 = wm1 * 16 + (lane >> 2);
                int colL = wn1 * 32 + j * 8 + (lane & 3) * 2;
                int gc = kc * 64 + colL;
                float bb0 = b1[gc], bb1 = b1[gc + 1];
                uint32_t plo = f2h2(fmaxf(a1[j][0] + bb0, 0.f), fmaxf(a1[j][1] + bb1, 0.f));
                uint32_t phi = f2h2(fmaxf(a1[j][2] + bb0, 0.f), fmaxf(a1[j][3] + bb1, 0.f));
                int gg = colL >> 3;
                uint32_t sw = (uint32_t)(((gg ^ (row0 & 7)) << 4) + (colL & 7) * 2);
                st1s(TCH + (uint32_t)(row0 * 128) + sw, plo);
                st1s(TCH + (uint32_t)((row0 + 8) * 128) + sw, phi);
            }
            // S3: wait W2even; issue W2odd; GEMM2 even pieces
            CPA_WAIT(0);
            __syncthreads();
            issueW2h(W2, kc, 1, B1);
            g2half(B0, 0);
            // S4: wait W2odd; issue next W1a; GEMM2 odd pieces
            CPA_WAIT(0);
            __syncthreads();
            if (kc < 7)     issueW1h(W1, kc + 1, 0, B0);
            else if (l < 7) issueW1h(g_W1ph + (size_t)(l + 1) * 8 * 4 * 4096, 0, 0, B0);
            g2half(B1, 1);
        }
        const float* b2 = b2g + l * 256;
#pragma unroll
        for (int i = 0; i < 2; i++)
#pragma unroll
            for (int j = 0; j < 8; j++) {
                int col = warp_n * 64 + j * 8 + (lane & 3) * 2;
                float b0 = b2[col], b1v = b2[col + 1];
                hreg[i * 8 + j][0] += b0;  hreg[i * 8 + j][1] += b1v;
                hreg[i * 8 + j][2] += b0;  hreg[i * 8 + j][3] += b1v;
            }
    }

    // ================= final LN + head =================
    {
        float rs_[4] = {0.f, 0.f, 0.f, 0.f}, rq_[4] = {0.f, 0.f, 0.f, 0.f};
#pragma unroll
        for (int i = 0; i < 2; i++)
#pragma unroll
            for (int j = 0; j < 8; j++) {
                float v0 = hreg[i * 8 + j][0], v1 = hreg[i * 8 + j][1];
                float v2 = hreg[i * 8 + j][2], v3 = hreg[i * 8 + j][3];
                rs_[i * 2 + 0] += v0 + v1;  rq_[i * 2 + 0] += v0 * v0 + v1 * v1;
                rs_[i * 2 + 1] += v2 + v3;  rq_[i * 2 + 1] += v2 * v2 + v3 * v3;
            }
#pragma unroll
        for (int t = 0; t < 4; t++)
#pragma unroll
            for (int o = 1; o <= 2; o <<= 1) {
                rs_[t] += __shfl_xor_sync(0xffffffffu, rs_[t], o);
                rq_[t] += __shfl_xor_sync(0xffffffffu, rq_[t], o);
            }
        if ((lane & 3) == 0) {
#pragma unroll
            for (int i = 0; i < 2; i++)
#pragma unroll
                for (int h = 0; h < 2; h++) {
                    int rloc = warp_m * 32 + i * 16 + h * 8 + (lane >> 2);
                    red_s[rloc * 4 + warp_n] = rs_[i * 2 + h];
                    red_q[rloc * 4 + warp_n] = rq_[i * 2 + h];
                }
        }
        __syncthreads();
        float hd0[4] = {0.f, 0.f, 0.f, 0.f}, hd1[4] = {0.f, 0.f, 0.f, 0.f};
#pragma unroll
        for (int i = 0; i < 2; i++)
#pragma unroll
            for (int h = 0; h < 2; h++) {
                int rloc = warp_m * 32 + i * 16 + h * 8 + (lane >> 2);
                float s = red_s[rloc * 4 + 0] + red_s[rloc * 4 + 1]
                        + red_s[rloc * 4 + 2] + red_s[rloc * 4 + 3];
                float q = red_q[rloc * 4 + 0] + red_q[rloc * 4 + 1]
                        + red_q[rloc * 4 + 2] + red_q[rloc * 4 + 3];
                float mu = s * (1.f / 256.f);
                float rinv = rsqrtf(q * (1.f / 256.f) - mu * mu + 1e-5f);
#pragma unroll
                for (int j = 0; j < 8; j++) {
                    int col = warp_n * 64 + j * 8 + (lane & 3) * 2;
                    float y0 = (hreg[i * 8 + j][h * 2 + 0] - mu) * rinv * gf[col]     + betf[col];
                    float y1 = (hreg[i * 8 + j][h * 2 + 1] - mu) * rinv * gf[col + 1] + betf[col + 1];
                    hd0[i * 2 + h] += y0 * Wh[col * 2 + 0] + y1 * Wh[col * 2 + 2];
                    hd1[i * 2 + h] += y0 * Wh[col * 2 + 1] + y1 * Wh[col * 2 + 3];
                }
            }
#pragma unroll
        for (int t = 0; t < 4; t++)
#pragma unroll
            for (int o = 1; o <= 2; o <<= 1) {
                hd0[t] += __shfl_xor_sync(0xffffffffu, hd0[t], o);
                hd1[t] += __shfl_xor_sync(0xffffffffu, hd1[t], o);
            }
        __syncthreads();
        if ((lane & 3) == 0) {
#pragma unroll
            for (int i = 0; i < 2; i++)
#pragma unroll
                for (int h = 0; h < 2; h++) {
                    int rloc = warp_m * 32 + i * 16 + h * 8 + (lane >> 2);
                    red_s[rloc * 4 + warp_n] = hd0[i * 2 + h];
                    red_q[rloc * 4 + warp_n] = hd1[i * 2 + h];
                }
        }
        __syncthreads();
        if (tid < 64) {
            float s0 = red_s[tid * 4 + 0] + red_s[tid * 4 + 1]
                     + red_s[tid * 4 + 2] + red_s[tid * 4 + 3];
            float s1 = red_q[tid * 4 + 0] + red_q[tid * 4 + 1]
                     + red_q[tid * 4 + 2] + red_q[tid * 4 + 3];
            out[(bm + tid) * 2 + 0] = s0 + bh[0];
            out[(bm + tid) * 2 + 1] = s1 + bh[1];
        }
    }
}

// ---------------- launch ----------------
extern "C" void kernel_launch(void* const* d_in, const int* in_sizes, int n_in,
                              void* d_out, int out_size) {
    const float* x_num   = (const float*)d_in[0];
    const int*   xidx    = (const int*)  d_in[1];
    const float* w_num   = (const float*)d_in[2];
    const float* b_num   = (const float*)d_in[3];
    const float* cat_emb = (const float*)d_in[4];
    const float* W_first = (const float*)d_in[5];
    const float* b_first = (const float*)d_in[6];
    const float* ln_g    = (const float*)d_in[7];
    const float* ln_b    = (const float*)d_in[8];
    const float* W1s     = (const float*)d_in[9];
    const float* b1s     = (const float*)d_in[10];
    const float* W2s     = (const float*)d_in[11];
    const float* b2s     = (const float*)d_in[12];
    const float* g_f     = (const float*)d_in[13];
    const float* beta_f  = (const float*)d_in[14];
    const float* W_head  = (const float*)d_in[15];
    const float* b_head  = (const float*)d_in[16];

    cudaFuncSetAttribute(fused_net, cudaFuncAttributeMaxDynamicSharedMemorySize, SMEM_DYN);

    prep_anum<<<32, 256>>>(w_num, W_first);
    prep_c1<<<32, 256>>>(b_num, W_first);
    prep_c2<<<1, 256>>>(b_first);
    pack_w1<<<1024, 256>>>(W1s);
    pack_w2<<<1024, 256>>>(W2s);
    pack_wf<<<1024, 256>>>(W_first + (size_t)8192 * 256);

    fused_net<<<256, 256, SMEM_DYN>>>(
        x_num, xidx, cat_emb, b1s, b2s, ln_g, ln_b,
        g_f, beta_f, W_head, b_head, (float*)d_out);
}

// round 11
// speedup vs baseline: 1.9929x; 1.0295x over previous
#include <cuda_runtime.h>
#include <cuda_fp16.h>
#include <cstdint>

// ---------------- problem constants ----------------
static constexpr int Bsz = 16384;
static constexpr int SMEM_DYN = 104 * 1024 + 1024;  // layers: 32+8+32+32 K; phase0: 80K

// ---------------- device scratch ----------------
__device__ float  g_Anum[32 * 256];
__device__ float  g_c[256];
__device__ float  g_cpart[32 * 256];
__device__ __half g_W1ph[8 * 8 * 4 * 64 * 64];    // [l][kc][kb][n64][k64] swizzled fp16
__device__ __half g_W2ph[8 * 8 * 8 * 32 * 64];    // [l][kc][piece][n32][k64]
__device__ __half g_Wfph[65 * 256 * 64];          // [chunk][n256][k64] (chunk0 = numeric+zeros)

// ---------------- PTX helpers ----------------
__device__ __forceinline__ uint32_t sm32(const void* p) {
    uint32_t a;
    asm("{ .reg .u64 t; cvta.to.shared.u64 t, %1; cvt.u32.u64 %0, t; }" : "=r"(a) : "l"(p));
    return a;
}
__device__ __forceinline__ void cpa16(uint32_t dst, const void* src) {
    asm volatile("cp.async.cg.shared.global [%0], [%1], 16;" :: "r"(dst), "l"(src));
}
#define CPA_COMMIT() asm volatile("cp.async.commit_group;" ::: "memory")
#define CPA_WAIT(n)  asm volatile("cp.async.wait_group %0;" :: "n"(n) : "memory")

__device__ __forceinline__ void ldm4(uint32_t (&r)[4], uint32_t addr) {
    asm volatile("ldmatrix.sync.aligned.m8n8.x4.shared.b16 {%0,%1,%2,%3}, [%4];"
                 : "=r"(r[0]), "=r"(r[1]), "=r"(r[2]), "=r"(r[3]) : "r"(addr));
}
__device__ __forceinline__ void mma_f16(float (&d)[4], const uint32_t (&a)[4],
                                        uint32_t b0, uint32_t b1) {
    asm volatile("mma.sync.aligned.m16n8k16.row.col.f32.f16.f16.f32 "
                 "{%0,%1,%2,%3}, {%4,%5,%6,%7}, {%8,%9}, {%0,%1,%2,%3};"
                 : "+f"(d[0]), "+f"(d[1]), "+f"(d[2]), "+f"(d[3])
                 : "r"(a[0]), "r"(a[1]), "r"(a[2]), "r"(a[3]), "r"(b0), "r"(b1));
}
__device__ __forceinline__ uint32_t f2h2(float lo, float hi) {
    uint32_t r;
    asm("cvt.rn.f16x2.f32 %0, %1, %2;" : "=r"(r) : "f"(hi), "f"(lo));
    return r;
}
__device__ __forceinline__ void st1s(uint32_t a, uint32_t v) {
    asm volatile("st.shared.b32 [%0], %1;" :: "r"(a), "r"(v));
}
__device__ __forceinline__ void st4s(uint32_t a, uint32_t x, uint32_t y, uint32_t z, uint32_t w) {
    asm volatile("st.shared.v4.b32 [%0], {%1,%2,%3,%4};" :: "r"(a), "r"(x), "r"(y), "r"(z), "r"(w));
}

// ---------------- prep kernels (3 launches) ----------------
// blocks 0-31: A_num fold; blocks 32-63: c partials
__global__ void prep_fold(const float* __restrict__ w_num, const float* __restrict__ b_num,
                          const float* __restrict__ W_first) {
    int j = threadIdx.x;
    if (blockIdx.x < 32) {
        int f = blockIdx.x;
        const float* Wf = W_first + (size_t)f * 256 * 256 + j;
        const float* wn = w_num + f * 256;
        float acc = 0.f;
        for (int d = 0; d < 256; d++) acc = fmaf(wn[d], Wf[(size_t)d * 256], acc);
        g_Anum[f * 256 + j] = acc;
    } else {
        int b = blockIdx.x - 32;
        const float* W = W_first + (size_t)b * 256 * 256 + j;
        const float* bn = b_num + b * 256;
        float acc = 0.f;
        for (int k = 0; k < 256; k++) acc = fmaf(bn[k], W[(size_t)k * 256], acc);
        g_cpart[b * 256 + j] = acc;
    }
}
__global__ void prep_c2(const float* __restrict__ b_first) {
    int j = threadIdx.x;
    float acc = b_first[j];
    for (int b = 0; b < 32; b++) acc += g_cpart[b * 256 + j];
    g_c[j] = acc;
}
__device__ __forceinline__ int swzk(int j, int n) {
    return (((j >> 3) ^ (n & 7)) << 3) | (j & 7);
}
static constexpr int NW1 = 524288, NW2 = 524288, NWF = 65 * 256 * 32;
__global__ void pack_all(const float* __restrict__ W1s, const float* __restrict__ W2s,
                         const float* __restrict__ Wcat) {
    for (int t = blockIdx.x * blockDim.x + threadIdx.x; t < NW1 + NW2 + NWF;
         t += gridDim.x * blockDim.x) {
        if (t < NW1) {
            int i = t;
            int j = (i & 31) * 2, n = (i >> 5) & 63, kb = (i >> 11) & 3, kc = (i >> 13) & 7, l = i >> 16;
            int k = swzk(j, n);
            const float* s = W1s + (size_t)(l * 256 + kb * 64 + k) * 512 + kc * 64 + n;
            ((__half2*)g_W1ph)[i] = __floats2half2_rn(s[0], s[512]);
        } else if (t < NW1 + NW2) {
            int i = t - NW1;
            int j = (i & 31) * 2, n = (i >> 5) & 31, p = (i >> 10) & 7, kc = (i >> 13) & 7, l = i >> 16;
            int k = swzk(j, n);
            const float* s = W2s + (size_t)(l * 512 + kc * 64 + k) * 256 + p * 32 + n;
            ((__half2*)g_W2ph)[i] = __floats2half2_rn(s[0], s[256]);
        } else {
            int i = t - NW1 - NW2;
            int j = (i & 31) * 2, n = (i >> 5) & 255, c = i >> 13;
            int k = swzk(j, n);
            float v0, v1;
            if (c == 0) {
                v0 = (k < 32) ? g_Anum[k * 256 + n] : 0.f;
                v1 = (k < 32) ? g_Anum[(k + 1) * 256 + n] : 0.f;
            } else {
                const float* s = Wcat + (size_t)((c - 1) * 64 + k) * 256 + n;
                v0 = s[0]; v1 = s[256];
            }
            ((__half2*)g_Wfph)[i] = __floats2half2_rn(v0, v1);
        }
    }
}

// =====================================================================
// Persistent fused network kernel (fp16 operands, fp32 accum).
// One CTA = 64 rows, 256 threads, occ 2. Full 32KB weight buffers,
// 2 syncs per kc, loads fully overlapped with the opposite GEMM.
// =====================================================================
__global__ __launch_bounds__(256, 2) void fused_net(
    const float* __restrict__ xnum, const int* __restrict__ xidx,
    const float* __restrict__ cemb,
    const float* __restrict__ b1g, const float* __restrict__ b2g,
    const float* __restrict__ lng, const float* __restrict__ lnbet,
    const float* __restrict__ gf,  const float* __restrict__ betf,
    const float* __restrict__ Wh,  const float* __restrict__ bh,
    float* __restrict__ out)
{
    extern __shared__ float dsm[];
    __shared__ float red_s[64 * 4], red_q[64 * 4];
    __shared__ int s_xidx[64 * 16];
    uint32_t raw  = sm32(dsm);
    uint32_t base = (raw + 1023u) & ~1023u;
    // layers: LNB 32K | TCH 8K | B0 32K | B1 32K  (104K)
    const uint32_t LNB = base;
    const uint32_t TCH = base + 32768u;
    const uint32_t B0  = base + 40960u;
    const uint32_t B1  = base + 73728u;
    // phase 0: A0 8K | A1 8K | Bb0 32K | Bb1 32K  (80K)
    const uint32_t P0A = base;
    const uint32_t P0B = base + 16384u;

    int tid = threadIdx.x, wid = tid >> 5, lane = tid & 31;
    int bm = blockIdx.x * 64;
    int warp_m = wid & 1, warp_n = wid >> 1;   // phase0/GEMM2: 2m x 4n (64 x 256)
    int wm1 = wid & 3,    wn1 = wid >> 2;      // GEMM1: 4m x 2n (64 x 64)
    int lr = lane & 7, lh = (lane >> 3) & 1, lg = lane >> 4;

    float hreg[16][4];
#pragma unroll
    for (int t = 0; t < 16; t++)
#pragma unroll
        for (int q = 0; q < 4; q++) hreg[t][q] = 0.f;

    for (int i = tid; i < 64 * 16; i += 256) s_xidx[i] = xidx[bm * 16 + i];
    __syncthreads();

    // ================= Phase 0: first GEMM, 65 chunks of 64 k =================
    {
        int ar = tid >> 2, aq = tid & 3;
        float4 R4[4];
        auto ldgA = [&](int c) {
            if (c == 0) {
                if (aq < 2) {
                    const float4* s = (const float4*)(xnum + (size_t)(bm + ar) * 32 + aq * 16);
#pragma unroll
                    for (int i = 0; i < 4; i++) R4[i] = s[i];
                } else {
#pragma unroll
                    for (int i = 0; i < 4; i++) R4[i] = make_float4(0.f, 0.f, 0.f, 0.f);
                }
            } else {
                int cc = c - 1, f = cc >> 2, d0 = (cc & 3) << 6;
                const float4* s = (const float4*)(cemb + (size_t)s_xidx[ar * 16 + f] * 256 + d0 + aq * 16);
#pragma unroll
                for (int i = 0; i < 4; i++) R4[i] = s[i];
            }
        };
        auto stsA = [&](int b) {
            uint32_t bufa = P0A + (uint32_t)b * 8192u + (uint32_t)ar * 128u;
#pragma unroll
            for (int t = 0; t < 2; t++) {
                int g = aq * 2 + t;
                uint32_t a = bufa + (uint32_t)((g ^ (ar & 7)) << 4);
                st4s(a, f2h2(R4[2 * t].x, R4[2 * t].y), f2h2(R4[2 * t].z, R4[2 * t].w),
                        f2h2(R4[2 * t + 1].x, R4[2 * t + 1].y), f2h2(R4[2 * t + 1].z, R4[2 * t + 1].w));
            }
        };
        auto cpB = [&](int c, int b) {
            const float4* src = (const float4*)(g_Wfph + (size_t)c * 16384) + tid;
            uint32_t Bd = P0B + (uint32_t)b * 32768u + (uint32_t)tid * 16u;
#pragma unroll
            for (int i = 0; i < 8; i++) cpa16(Bd + (uint32_t)i * 4096u, src + i * 256);
            CPA_COMMIT();
        };

        ldgA(0);
        cpB(0, 0); cpB(1, 1);
#pragma unroll 1
        for (int c = 0; c <= 64; c++) {
            int b = c & 1;
            stsA(b);
            if (c < 64) ldgA(c + 1);
            if (c + 1 <= 64) CPA_WAIT(1); else CPA_WAIT(0);
            __syncthreads();
            uint32_t Ab = P0A + (uint32_t)b * 8192u;
            uint32_t Bb = P0B + (uint32_t)b * 32768u;
#pragma unroll
            for (int s = 0; s < 4; s++) {
                int g = s * 2 + lg;
                uint32_t af[2][4];
#pragma unroll
                for (int i = 0; i < 2; i++) {
                    int R = warp_m * 32 + i * 16 + lr + lh * 8;
                    ldm4(af[i], Ab + (uint32_t)(R * 128 + ((g ^ (R & 7)) << 4)));
                }
                uint32_t bf[8][2];
#pragma unroll
                for (int p = 0; p < 4; p++) {
                    int n = warp_n * 64 + p * 16 + lr + lh * 8;
                    uint32_t t4[4];
                    ldm4(t4, Bb + (uint32_t)(n * 128 + ((g ^ (n & 7)) << 4)));
                    bf[2 * p][0] = t4[0]; bf[2 * p][1] = t4[2];
                    bf[2 * p + 1][0] = t4[1]; bf[2 * p + 1][1] = t4[3];
                }
#pragma unroll
                for (int i = 0; i < 2; i++)
#pragma unroll
                    for (int j = 0; j < 8; j++)
                        mma_f16(hreg[i * 8 + j], af[i], bf[j][0], bf[j][1]);
            }
            __syncthreads();
            if (c + 2 <= 64) cpB(c + 2, b);
        }
#pragma unroll
        for (int i = 0; i < 2; i++)
#pragma unroll
            for (int j = 0; j < 8; j++) {
                int col = warp_n * 64 + j * 8 + (lane & 3) * 2;
                float b0 = g_c[col], b1 = g_c[col + 1];
                hreg[i * 8 + j][0] += b0; hreg[i * 8 + j][1] += b1;
                hreg[i * 8 + j][2] += b0; hreg[i * 8 + j][3] += b1;
            }
    }

    // ---- full 32KB weight loaders ----
    auto issueW1f = [&](const __half* W1, int kc, uint32_t B) {
        const float4* src = (const float4*)(W1 + (size_t)kc * 16384) + tid;
#pragma unroll
        for (int i = 0; i < 8; i++) cpa16(B + (uint32_t)(tid * 16 + i * 4096), src + i * 256);
        CPA_COMMIT();
    };
    auto issueW2f = [&](const __half* W2, int kc, uint32_t B) {
        const float4* src = (const float4*)(W2 + (size_t)kc * 16384) + tid;
#pragma unroll
        for (int i = 0; i < 8; i++) cpa16(B + (uint32_t)(tid * 16 + i * 4096), src + i * 256);
        CPA_COMMIT();
    };

    // ---- LN from hreg -> LNB (fp16) ----
    auto do_ln = [&](const float* gam, const float* bet) {
        float rs_[4] = {0.f, 0.f, 0.f, 0.f}, rq_[4] = {0.f, 0.f, 0.f, 0.f};
#pragma unroll
        for (int i = 0; i < 2; i++)
#pragma unroll
            for (int j = 0; j < 8; j++) {
                float v0 = hreg[i * 8 + j][0], v1 = hreg[i * 8 + j][1];
                float v2 = hreg[i * 8 + j][2], v3 = hreg[i * 8 + j][3];
                rs_[i * 2 + 0] += v0 + v1;  rq_[i * 2 + 0] += v0 * v0 + v1 * v1;
                rs_[i * 2 + 1] += v2 + v3;  rq_[i * 2 + 1] += v2 * v2 + v3 * v3;
            }
#pragma unroll
        for (int t = 0; t < 4; t++)
#pragma unroll
            for (int o = 1; o <= 2; o <<= 1) {
                rs_[t] += __shfl_xor_sync(0xffffffffu, rs_[t], o);
                rq_[t] += __shfl_xor_sync(0xffffffffu, rq_[t], o);
            }
        if ((lane & 3) == 0) {
#pragma unroll
            for (int i = 0; i < 2; i++)
#pragma unroll
                for (int h = 0; h < 2; h++) {
                    int rloc = warp_m * 32 + i * 16 + h * 8 + (lane >> 2);
                    red_s[rloc * 4 + warp_n] = rs_[i * 2 + h];
                    red_q[rloc * 4 + warp_n] = rq_[i * 2 + h];
                }
        }
        __syncthreads();
#pragma unroll
        for (int i = 0; i < 2; i++)
#pragma unroll
            for (int h = 0; h < 2; h++) {
                int rloc = warp_m * 32 + i * 16 + h * 8 + (lane >> 2);
                float s = red_s[rloc * 4 + 0] + red_s[rloc * 4 + 1]
                        + red_s[rloc * 4 + 2] + red_s[rloc * 4 + 3];
                float q = red_q[rloc * 4 + 0] + red_q[rloc * 4 + 1]
                        + red_q[rloc * 4 + 2] + red_q[rloc * 4 + 3];
                float mu = s * (1.f / 256.f);
                float rinv = rsqrtf(q * (1.f / 256.f) - mu * mu + 1e-5f);
#pragma unroll
                for (int j = 0; j < 8; j++) {
                    int col = warp_n * 64 + j * 8 + (lane & 3) * 2;
                    float y0 = (hreg[i * 8 + j][h * 2 + 0] - mu) * rinv * gam[col]     + bet[col];
                    float y1 = (hreg[i * 8 + j][h * 2 + 1] - mu) * rinv * gam[col + 1] + bet[col + 1];
                    int kcol = col & 63, kb = col >> 6, gg = kcol >> 3;
                    uint32_t addr = LNB + (uint32_t)(kb * 8192 + rloc * 128
                                   + ((gg ^ (rloc & 7)) << 4) + (kcol & 7) * 2);
                    st1s(addr, f2h2(y0, y1));
                }
            }
        __syncthreads();
    };

    // GEMM1 full: 4 kb blocks from one 32KB buffer
    float a1[4][4];
    auto g1full = [&](uint32_t B) {
#pragma unroll
        for (int kb = 0; kb < 4; kb++) {
#pragma unroll
            for (int s = 0; s < 4; s++) {
                int g = s * 2 + lg;
                uint32_t af[4];
                int R = wm1 * 16 + lr + lh * 8;
                ldm4(af, LNB + (uint32_t)(kb * 8192 + R * 128 + ((g ^ (R & 7)) << 4)));
                uint32_t bf[4][2];
#pragma unroll
                for (int pp = 0; pp < 2; pp++) {
                    int n = wn1 * 32 + pp * 16 + lr + lh * 8;
                    uint32_t t4[4];
                    ldm4(t4, B + (uint32_t)(kb * 8192 + n * 128 + ((g ^ (n & 7)) << 4)));
                    bf[2 * pp][0] = t4[0]; bf[2 * pp][1] = t4[2];
                    bf[2 * pp + 1][0] = t4[1]; bf[2 * pp + 1][1] = t4[3];
                }
#pragma unroll
                for (int j = 0; j < 4; j++) mma_f16(a1[j], af, bf[j][0], bf[j][1]);
            }
        }
    };
    // GEMM2 full: warp's two 32-n pieces (2*warp_n, 2*warp_n+1)
    auto g2full = [&](uint32_t B) {
#pragma unroll
        for (int p = 0; p < 2; p++) {
            uint32_t Bp = B + (uint32_t)(2 * warp_n + p) * 4096u;
#pragma unroll
            for (int s = 0; s < 4; s++) {
                int g = s * 2 + lg;
                uint32_t af[2][4];
#pragma unroll
                for (int i = 0; i < 2; i++) {
                    int R = warp_m * 32 + i * 16 + lr + lh * 8;
                    ldm4(af[i], TCH + (uint32_t)(R * 128 + ((g ^ (R & 7)) << 4)));
                }
                uint32_t bf[4][2];
#pragma unroll
                for (int pp = 0; pp < 2; pp++) {
                    int nl = pp * 16 + lr + lh * 8;
                    uint32_t t4[4];
                    ldm4(t4, Bp + (uint32_t)(nl * 128 + ((g ^ (nl & 7)) << 4)));
                    bf[2 * pp][0] = t4[0]; bf[2 * pp][1] = t4[2];
                    bf[2 * pp + 1][0] = t4[1]; bf[2 * pp + 1][1] = t4[3];
                }
#pragma unroll
                for (int i = 0; i < 2; i++)
#pragma unroll
                    for (int jj = 0; jj < 4; jj++)
                        mma_f16(hreg[i * 8 + p * 4 + jj], af[i], bf[jj][0], bf[jj][1]);
            }
        }
    };

    // prologue: W1 of layer 0, kc 0 -> B0
    issueW1f(g_W1ph, 0, B0);

    // ================= 8 residual layers (8 kc of 64 each) =================
#pragma unroll 1
    for (int l = 0; l < 8; l++) {
        do_ln(lng + l * 256, lnbet + l * 256);
        const __half* W1 = g_W1ph + (size_t)l * 8 * 16384;
        const __half* W2 = g_W2ph + (size_t)l * 8 * 16384;
        const float*  b1 = b1g + l * 512;
#pragma unroll 1
        for (int kc = 0; kc < 8; kc++) {
#pragma unroll
            for (int j = 0; j < 4; j++)
#pragma unroll
                for (int q = 0; q < 4; q++) a1[j][q] = 0.f;
            // ---- S1: wait W1(kc); issue W2(kc)->B1; GEMM1 full; relu+bias -> TCH ----
            CPA_WAIT(0);
            __syncthreads();
            issueW2f(W2, kc, B1);
            g1full(B0);
#pragma unroll
            for (int j = 0; j < 4; j++) {
                int row0 = wm1 * 16 + (lane >> 2);
                int colL = wn1 * 32 + j * 8 + (lane & 3) * 2;
                int gc = kc * 64 + colL;
                float bb0 = b1[gc], bb1 = b1[gc + 1];
                uint32_t plo = f2h2(fmaxf(a1[j][0] + bb0, 0.f), fmaxf(a1[j][1] + bb1, 0.f));
                uint32_t phi = f2h2(fmaxf(a1[j][2] + bb0, 0.f), fmaxf(a1[j][3] + bb1, 0.f));
                int gg = colL >> 3;
                uint32_t sw = (uint32_t)(((gg ^ (row0 & 7)) << 4) + (colL & 7) * 2);
                st1s(TCH + (uint32_t)(row0 * 128) + sw, plo);
                st1s(TCH + (uint32_t)((row0 + 8) * 128) + sw, phi);
            }
            // ---- S2: wait W2(kc); issue W1(kc+1)->B0; GEMM2 full ----
            CPA_WAIT(0);
            __syncthreads();
            if (kc < 7)     issueW1f(W1, kc + 1, B0);
            else if (l < 7) issueW1f(g_W1ph + (size_t)(l + 1) * 8 * 16384, 0, B0);
            g2full(B1);
        }
        const float* b2 = b2g + l * 256;
#pragma unroll
        for (int i = 0; i < 2; i++)
#pragma unroll
            for (int j = 0; j < 8; j++) {
                int col = warp_n * 64 + j * 8 + (lane & 3) * 2;
                float b0 = b2[col], b1v = b2[col + 1];
                hreg[i * 8 + j][0] += b0;  hreg[i * 8 + j][1] += b1v;
                hreg[i * 8 + j][2] += b0;  hreg[i * 8 + j][3] += b1v;
            }
    }

    // ================= final LN + head =================
    {
        float rs_[4] = {0.f, 0.f, 0.f, 0.f}, rq_[4] = {0.f, 0.f, 0.f, 0.f};
#pragma unroll
        for (int i = 0; i < 2; i++)
#pragma unroll
            for (int j = 0; j < 8; j++) {
                float v0 = hreg[i * 8 + j][0], v1 = hreg[i * 8 + j][1];
                float v2 = hreg[i * 8 + j][2], v3 = hreg[i * 8 + j][3];
                rs_[i * 2 + 0] += v0 + v1;  rq_[i * 2 + 0] += v0 * v0 + v1 * v1;
                rs_[i * 2 + 1] += v2 + v3;  rq_[i * 2 + 1] += v2 * v2 + v3 * v3;
            }
#pragma unroll
        for (int t = 0; t < 4; t++)
#pragma unroll
            for (int o = 1; o <= 2; o <<= 1) {
                rs_[t] += __shfl_xor_sync(0xffffffffu, rs_[t], o);
                rq_[t] += __shfl_xor_sync(0xffffffffu, rq_[t], o);
            }
        if ((lane & 3) == 0) {
#pragma unroll
            for (int i = 0; i < 2; i++)
#pragma unroll
                for (int h = 0; h < 2; h++) {
                    int rloc = warp_m * 32 + i * 16 + h * 8 + (lane >> 2);
                    red_s[rloc * 4 + warp_n] = rs_[i * 2 + h];
                    red_q[rloc * 4 + warp_n] = rq_[i * 2 + h];
                }
        }
        __syncthreads();
        float hd0[4] = {0.f, 0.f, 0.f, 0.f}, hd1[4] = {0.f, 0.f, 0.f, 0.f};
#pragma unroll
        for (int i = 0; i < 2; i++)
#pragma unroll
            for (int h = 0; h < 2; h++) {
                int rloc = warp_m * 32 + i * 16 + h * 8 + (lane >> 2);
                float s = red_s[rloc * 4 + 0] + red_s[rloc * 4 + 1]
                        + red_s[rloc * 4 + 2] + red_s[rloc * 4 + 3];
                float q = red_q[rloc * 4 + 0] + red_q[rloc * 4 + 1]
                        + red_q[rloc * 4 + 2] + red_q[rloc * 4 + 3];
                float mu = s * (1.f / 256.f);
                float rinv = rsqrtf(q * (1.f / 256.f) - mu * mu + 1e-5f);
#pragma unroll
                for (int j = 0; j < 8; j++) {
                    int col = warp_n * 64 + j * 8 + (lane & 3) * 2;
                    float y0 = (hreg[i * 8 + j][h * 2 + 0] - mu) * rinv * gf[col]     + betf[col];
                    float y1 = (hreg[i * 8 + j][h * 2 + 1] - mu) * rinv * gf[col + 1] + betf[col + 1];
                    hd0[i * 2 + h] += y0 * Wh[col * 2 + 0] + y1 * Wh[col * 2 + 2];
                    hd1[i * 2 + h] += y0 * Wh[col * 2 + 1] + y1 * Wh[col * 2 + 3];
                }
            }
#pragma unroll
        for (int t = 0; t < 4; t++)
#pragma unroll
            for (int o = 1; o <= 2; o <<= 1) {
                hd0[t] += __shfl_xor_sync(0xffffffffu, hd0[t], o);
                hd1[t] += __shfl_xor_sync(0xffffffffu, hd1[t], o);
            }
        __syncthreads();
        if ((lane & 3) == 0) {
#pragma unroll
            for (int i = 0; i < 2; i++)
#pragma unroll
                for (int h = 0; h < 2; h++) {
                    int rloc = warp_m * 32 + i * 16 + h * 8 + (lane >> 2);
                    red_s[rloc * 4 + warp_n] = hd0[i * 2 + h];
                    red_q[rloc * 4 + warp_n] = hd1[i * 2 + h];
                }
        }
        __syncthreads();
        if (tid < 64) {
            float s0 = red_s[tid * 4 + 0] + red_s[tid * 4 + 1]
                     + red_s[tid * 4 + 2] + red_s[tid * 4 + 3];
            float s1 = red_q[tid * 4 + 0] + red_q[tid * 4 + 1]
                     + red_q[tid * 4 + 2] + red_q[tid * 4 + 3];
            out[(bm + tid) * 2 + 0] = s0 + bh[0];
            out[(bm + tid) * 2 + 1] = s1 + bh[1];
        }
    }
}

// ---------------- launch (4 kernels) ----------------
extern "C" void kernel_launch(void* const* d_in, const int* in_sizes, int n_in,
                              void* d_out, int out_size) {
    const float* x_num   = (const float*)d_in[0];
    const int*   xidx    = (const int*)  d_in[1];
    const float* w_num   = (const float*)d_in[2];
    const float* b_num   = (const float*)d_in[3];
    const float* cat_emb = (const float*)d_in[4];
    const float* W_first = (const float*)d_in[5];
    const float* b_first = (const float*)d_in[6];
    const float* ln_g    = (const float*)d_in[7];
    const float* ln_b    = (const float*)d_in[8];
    const float* W1s     = (const float*)d_in[9];
    const float* b1s     = (const float*)d_in[10];
    const float* W2s     = (const float*)d_in[11];
    const float* b2s     = (const float*)d_in[12];
    const float* g_f     = (const float*)d_in[13];
    const float* beta_f  = (const float*)d_in[14];
    const float* W_head  = (const float*)d_in[15];
    const float* b_head  = (const float*)d_in[16];

    cudaFuncSetAttribute(fused_net, cudaFuncAttributeMaxDynamicSharedMemorySize, SMEM_DYN);

    prep_fold<<<64, 256>>>(w_num, b_num, W_first);
    prep_c2<<<1, 256>>>(b_first);
    pack_all<<<1024, 256>>>(W1s, W2s, W_first + (size_t)8192 * 256);

    fused_net<<<256, 256, SMEM_DYN>>>(
        x_num, xidx, cat_emb, b1s, b2s, ln_g, ln_b,
        g_f, beta_f, W_head, b_head, (float*)d_out);
}